// round 7
// baseline (speedup 1.0000x reference)
#include <cuda_runtime.h>
#include <cstdint>
#include <math.h>

// Problem shape: q,k,v [2,16,2048,64] fp32
#define BB 2
#define HH 16
#define SS 2048
#define DD 64
#define BH (BB*HH)

#define NT 512          // threads per CTA (16 warps)
#define TQ 16           // q rows per CTA

#define LSTRIDE 2052    // logits row stride (2048+4): %32==4 -> conflict-free frag loads
#define QTS 68          // q tile stride (64+4)
#define RTS 68          // reduction row stride (64+4)

#define OFF_LOG 0
#define OFF_QT  (TQ*LSTRIDE)            // 32832 floats (sums[16]+part[256] later)
#define OFF_RED (OFF_QT + TQ*QTS)       // 33920
#define SMEM_F  (OFF_RED + 16*16*RTS/16*16)  // red = 16 warps * 16*RTS... see below
#define RED_F   (16 * TQ * RTS)         // 16 warps x [16][68] = 17408
#define SMEM_BYTES ((OFF_RED + RED_F) * 4)   // (33920+17408)*4 = 205312

// tf32-rounded operands.
__device__ unsigned g_qn[(size_t)BH * SS * DD];   // normalized q*10, [bh][s][d]
__device__ unsigned g_kn[(size_t)BH * DD * SS];   // normalized k, transposed [bh][d][s]
__device__ unsigned g_vr[(size_t)BH * SS * DD];   // v rounded, [bh][s][d]

static __device__ __forceinline__ unsigned tf32r(float f) {
    unsigned u; asm("cvt.rna.tf32.f32 %0, %1;" : "=r"(u) : "f"(f)); return u;
}
static __device__ __forceinline__ void mma_tf32(float& d0, float& d1, float& d2, float& d3,
                                                unsigned a0, unsigned a1, unsigned a2, unsigned a3,
                                                unsigned b0, unsigned b1) {
    asm volatile(
        "mma.sync.aligned.m16n8k8.row.col.f32.tf32.tf32.f32 "
        "{%0,%1,%2,%3}, {%4,%5,%6,%7}, {%8,%9}, {%0,%1,%2,%3};"
        : "+f"(d0), "+f"(d1), "+f"(d2), "+f"(d3)
        : "r"(a0), "r"(a1), "r"(a2), "r"(a3), "r"(b0), "r"(b1));
}
static __device__ __forceinline__ void stg_cs4(float* p, float4 v) {
    asm volatile("st.global.cs.v4.f32 [%0], {%1,%2,%3,%4};"
                 :: "l"(p), "f"(v.x), "f"(v.y), "f"(v.z), "f"(v.w) : "memory");
}

// ---------------------------------------------------------------------------
// Prep: L2-normalize q (x10) / k, round everything (incl. v) to tf32.
// One warp per 64-elem row.
// ---------------------------------------------------------------------------
__global__ void __launch_bounds__(256)
prep_kernel(const float* __restrict__ q, const float* __restrict__ k,
            const float* __restrict__ v) {
    const int warp = threadIdx.x >> 5;
    const int lane = threadIdx.x & 31;
    const long long id = (long long)blockIdx.x * 8 + warp;
    const long long nrows = (long long)BH * SS;
    const int seg = (int)(id / nrows);                    // 0=q, 1=k, 2=v
    const int row = (int)(id - (long long)seg * nrows);

    const float* src = (seg == 0) ? q : (seg == 1 ? k : v);
    const float2 v2 = ((const float2*)(src + (size_t)row * DD))[lane];

    if (seg == 2) {
        ((uint2*)(g_vr + (size_t)row * DD))[lane] = make_uint2(tf32r(v2.x), tf32r(v2.y));
        return;
    }
    float ss = v2.x * v2.x + v2.y * v2.y;
    #pragma unroll
    for (int o = 16; o; o >>= 1) ss += __shfl_xor_sync(0xffffffffu, ss, o);
    float scale = 1.0f / fmaxf(sqrtf(ss), 1e-12f);
    if (seg == 0) scale *= 10.0f;

    if (seg == 0) {
        ((uint2*)(g_qn + (size_t)row * DD))[lane] =
            make_uint2(tf32r(v2.x * scale), tf32r(v2.y * scale));
    } else {
        const int bh = row >> 11;
        const int s  = row & (SS - 1);
        unsigned* base = g_kn + (size_t)bh * DD * SS + s;
        base[(size_t)(2 * lane) * SS]     = tf32r(v2.x * scale);
        base[(size_t)(2 * lane + 1) * SS] = tf32r(v2.y * scale);
    }
}

// ---------------------------------------------------------------------------
// Attention: one CTA = 16 q rows of one (b,h). 16 warps, no K/V smem staging.
// ---------------------------------------------------------------------------
__global__ void __launch_bounds__(NT, 1)
attn_kernel(float* __restrict__ outp, float* __restrict__ score) {
    extern __shared__ float sm[];
    float* logits = sm + OFF_LOG;
    float* qt     = sm + OFF_QT;
    float* red    = sm + OFF_RED;

    const int t    = threadIdx.x;
    const int lane = t & 31;
    const int warp = t >> 5;     // 0..15
    const int gp   = lane >> 2;  // 0..7
    const int tid4 = lane & 3;   // 0..3

    const int bh = blockIdx.x >> 7;
    const int q0 = (blockIdx.x & 127) * TQ;

    const unsigned* qn = g_qn + (size_t)bh * SS * DD;
    const unsigned* kn = g_kn + (size_t)bh * DD * SS;
    const unsigned* vr = g_vr + (size_t)bh * SS * DD;

    // ---- stage q tile ----
    if (t < 256) {
        int qi = t >> 4, d4 = t & 15;
        uint4 x = *(const uint4*)(qn + (size_t)(q0 + qi) * DD + d4 * 4);
        *(uint4*)((unsigned*)qt + qi * QTS + d4 * 4) = x;
    }
    __syncthreads();

    // ---- A fragments: entire 16x64 Q tile in registers ----
    unsigned a[8][4];
    {
        const unsigned* qtu = (const unsigned*)qt;
        #pragma unroll
        for (int ks = 0; ks < 8; ks++) {
            a[ks][0] = qtu[gp * QTS + ks * 8 + tid4];
            a[ks][1] = qtu[(gp + 8) * QTS + ks * 8 + tid4];
            a[ks][2] = qtu[gp * QTS + ks * 8 + tid4 + 4];
            a[ks][3] = qtu[(gp + 8) * QTS + ks * 8 + tid4 + 4];
        }
    }

    // ========= Phase 1: logits = exp(Q@K^T), B-frags straight from gmem ======
    // Warp owns cols [warp*128, warp*128+128). Sync-free.
    float ps0 = 0.0f, ps1 = 0.0f;   // row sums for rows gp, gp+8
    {
        const int colbase = warp * 128;
        #pragma unroll
        for (int g = 0; g < 4; g++) {
            const int n0 = colbase + g * 32;
            float acc[4][4];
            #pragma unroll
            for (int i = 0; i < 4; i++)
                #pragma unroll
                for (int j = 0; j < 4; j++) acc[i][j] = 0.0f;

            #pragma unroll
            for (int ks = 0; ks < 8; ks++) {
                const unsigned* kr0 = kn + (size_t)(ks * 8 + tid4) * SS + n0 + gp;
                const unsigned* kr1 = kn + (size_t)(ks * 8 + 4 + tid4) * SS + n0 + gp;
                unsigned b[4][2];
                #pragma unroll
                for (int nt2 = 0; nt2 < 4; nt2++) {
                    b[nt2][0] = kr0[nt2 * 8];
                    b[nt2][1] = kr1[nt2 * 8];
                }
                #pragma unroll
                for (int nt2 = 0; nt2 < 4; nt2++)
                    mma_tf32(acc[nt2][0], acc[nt2][1], acc[nt2][2], acc[nt2][3],
                             a[ks][0], a[ks][1], a[ks][2], a[ks][3],
                             b[nt2][0], b[nt2][1]);
            }

            #pragma unroll
            for (int nt2 = 0; nt2 < 4; nt2++) {
                float e0 = __expf(acc[nt2][0]);
                float e1 = __expf(acc[nt2][1]);
                float e2 = __expf(acc[nt2][2]);
                float e3 = __expf(acc[nt2][3]);
                ps0 += e0 + e1;
                ps1 += e2 + e3;
                float* lg = logits + gp * LSTRIDE + n0 + nt2 * 8 + tid4 * 2;
                *(float2*)lg = make_float2(e0, e1);
                *(float2*)(lg + 8 * LSTRIDE) = make_float2(e2, e3);
            }
        }
    }

    // ---- row-sum reduction: quad shfl then across 16 warps ----
    ps0 += __shfl_xor_sync(0xffffffffu, ps0, 1);
    ps0 += __shfl_xor_sync(0xffffffffu, ps0, 2);
    ps1 += __shfl_xor_sync(0xffffffffu, ps1, 1);
    ps1 += __shfl_xor_sync(0xffffffffu, ps1, 2);
    float* sums = qt;          // 16 floats (qt dead: frags in regs)
    float* part = qt + 16;     // [16][16]
    __syncthreads();           // logits writes visible; qt reads done
    if (tid4 == 0) {
        part[warp * 16 + gp]     = ps0;
        part[warp * 16 + 8 + gp] = ps1;
    }
    __syncthreads();
    if (t < 16) {
        float s = 0.0f;
        #pragma unroll
        for (int w = 0; w < 16; w++) s += part[w * 16 + t];
        sums[t] = 1.0f / s;
    }
    __syncthreads();

    // ========= Phase 2: score writes (streaming), warp owns its col-slice ====
    {
        const int colbase = warp * 128;
        #pragma unroll
        for (int r = 0; r < TQ; r++) {
            float inv = sums[r];
            float4 x = *(const float4*)(logits + (size_t)r * LSTRIDE + colbase + lane * 4);
            x.x *= inv; x.y *= inv; x.z *= inv; x.w *= inv;
            stg_cs4(score + ((size_t)bh * SS + q0 + r) * SS + colbase + lane * 4, x);
        }
    }

    // ========= Phase 3: out = exp(L) @ V, B-frags from gmem. Sync-free. ======
    // Warp owns k rows [warp*128, warp*128+128), full N=64.
    float acc2[8][4];
    #pragma unroll
    for (int i = 0; i < 8; i++)
        #pragma unroll
        for (int j = 0; j < 4; j++) acc2[i][j] = 0.0f;

    #pragma unroll 4
    for (int ks2 = 0; ks2 < 16; ks2++) {
        const int kgl = warp * 128 + ks2 * 8;
        unsigned a0 = tf32r(logits[gp * LSTRIDE + kgl + tid4]);
        unsigned a1 = tf32r(logits[(gp + 8) * LSTRIDE + kgl + tid4]);
        unsigned a2 = tf32r(logits[gp * LSTRIDE + kgl + tid4 + 4]);
        unsigned a3 = tf32r(logits[(gp + 8) * LSTRIDE + kgl + tid4 + 4]);
        const unsigned* vr0 = vr + (size_t)(kgl + tid4) * DD + gp;
        const unsigned* vr1 = vr + (size_t)(kgl + 4 + tid4) * DD + gp;
        unsigned b[8][2];
        #pragma unroll
        for (int nt2 = 0; nt2 < 8; nt2++) {
            b[nt2][0] = vr0[nt2 * 8];
            b[nt2][1] = vr1[nt2 * 8];
        }
        #pragma unroll
        for (int nt2 = 0; nt2 < 8; nt2++)
            mma_tf32(acc2[nt2][0], acc2[nt2][1], acc2[nt2][2], acc2[nt2][3],
                     a0, a1, a2, a3, b[nt2][0], b[nt2][1]);
    }

    // ---- cross-warp reduction ----
    #pragma unroll
    for (int nt2 = 0; nt2 < 8; nt2++) {
        float* m = red + warp * (TQ * RTS) + gp * RTS + nt2 * 8 + tid4 * 2;
        *(float2*)m = make_float2(acc2[nt2][0], acc2[nt2][1]);
        *(float2*)(m + 8 * RTS) = make_float2(acc2[nt2][2], acc2[nt2][3]);
    }
    __syncthreads();
    {
        // 1024 outputs, 512 threads: 2 consecutive d each
        int e  = t * 2;
        int qi = e >> 6;          // 0..15
        int d  = e & 63;
        float2 s2 = make_float2(0.0f, 0.0f);
        #pragma unroll
        for (int w = 0; w < 16; w++) {
            float2 x = *(const float2*)(red + w * (TQ * RTS) + qi * RTS + d);
            s2.x += x.x; s2.y += x.y;
        }
        float inv = sums[qi];
        s2.x *= inv; s2.y *= inv;
        *(float2*)(outp + ((size_t)bh * SS + q0 + qi) * DD + d) = s2;
    }
}

// ---------------------------------------------------------------------------
extern "C" void kernel_launch(void* const* d_in, const int* in_sizes, int n_in,
                              void* d_out, int out_size) {
    const float* q = (const float*)d_in[0];
    const float* k = (const float*)d_in[1];
    const float* v = (const float*)d_in[2];

    float* outp  = (float*)d_out;                 // [B,H,S,D]
    float* score = outp + (size_t)BH * SS * DD;   // [B,H,S,S]

    cudaFuncSetAttribute(attn_kernel,
                         cudaFuncAttributeMaxDynamicSharedMemorySize, SMEM_BYTES);

    prep_kernel<<<(3 * BH * SS) / 8, 256>>>(q, k, v);
    attn_kernel<<<BH * (SS / TQ), NT, SMEM_BYTES>>>(outp, score);
}

// round 8
// speedup vs baseline: 1.1686x; 1.1686x over previous
#include <cuda_runtime.h>
#include <cstdint>
#include <math.h>

// Problem shape: q,k,v [2,16,2048,64] fp32
#define BB 2
#define HH 16
#define SS 2048
#define DD 64
#define BH (BB*HH)

#define NT 512          // threads per CTA (16 warps)
#define TQ 16           // q rows per CTA

#define LSTRIDE 2052    // logits row stride (2048+4)
#define QTS 68          // q tile stride (64+4)
#define RTS 68          // reduction row stride (64+4)

#define OFF_LOG 0
#define OFF_QT  (TQ*LSTRIDE)            // 32832
#define OFF_RED (OFF_QT + TQ*QTS)       // 33920
#define RED_F   (16 * TQ * RTS)         // 17408
#define SMEM_BYTES ((OFF_RED + RED_F) * 4)   // 205312

// tf32-rounded operands.
__device__ unsigned g_qn[(size_t)BH * SS * DD];   // normalized q*10, [bh][s][d]
__device__ unsigned g_kn[(size_t)BH * DD * SS];   // normalized k, transposed [bh][d][s]
__device__ unsigned g_vr[(size_t)BH * SS * DD];   // v rounded, [bh][s][d]

static __device__ __forceinline__ unsigned tf32r(float f) {
    unsigned u; asm("cvt.rna.tf32.f32 %0, %1;" : "=r"(u) : "f"(f)); return u;
}
static __device__ __forceinline__ void mma_tf32(float& d0, float& d1, float& d2, float& d3,
                                                unsigned a0, unsigned a1, unsigned a2, unsigned a3,
                                                unsigned b0, unsigned b1) {
    asm volatile(
        "mma.sync.aligned.m16n8k8.row.col.f32.tf32.tf32.f32 "
        "{%0,%1,%2,%3}, {%4,%5,%6,%7}, {%8,%9}, {%0,%1,%2,%3};"
        : "+f"(d0), "+f"(d1), "+f"(d2), "+f"(d3)
        : "r"(a0), "r"(a1), "r"(a2), "r"(a3), "r"(b0), "r"(b1));
}
static __device__ __forceinline__ void stg_cs4(float* p, float4 v) {
    asm volatile("st.global.cs.v4.f32 [%0], {%1,%2,%3,%4};"
                 :: "l"(p), "f"(v.x), "f"(v.y), "f"(v.z), "f"(v.w) : "memory");
}

// ---------------------------------------------------------------------------
// Prep: L2-normalize q (x10) / k, round everything (incl. v) to tf32.
// ---------------------------------------------------------------------------
__global__ void __launch_bounds__(256)
prep_kernel(const float* __restrict__ q, const float* __restrict__ k,
            const float* __restrict__ v) {
    const int warp = threadIdx.x >> 5;
    const int lane = threadIdx.x & 31;
    const long long id = (long long)blockIdx.x * 8 + warp;
    const long long nrows = (long long)BH * SS;
    const int seg = (int)(id / nrows);                    // 0=q, 1=k, 2=v
    const int row = (int)(id - (long long)seg * nrows);

    const float* src = (seg == 0) ? q : (seg == 1 ? k : v);
    const float2 v2 = ((const float2*)(src + (size_t)row * DD))[lane];

    if (seg == 2) {
        ((uint2*)(g_vr + (size_t)row * DD))[lane] = make_uint2(tf32r(v2.x), tf32r(v2.y));
        return;
    }
    float ss = v2.x * v2.x + v2.y * v2.y;
    #pragma unroll
    for (int o = 16; o; o >>= 1) ss += __shfl_xor_sync(0xffffffffu, ss, o);
    float scale = 1.0f / fmaxf(sqrtf(ss), 1e-12f);
    if (seg == 0) scale *= 10.0f;

    if (seg == 0) {
        ((uint2*)(g_qn + (size_t)row * DD))[lane] =
            make_uint2(tf32r(v2.x * scale), tf32r(v2.y * scale));
    } else {
        const int bh = row >> 11;
        const int s  = row & (SS - 1);
        unsigned* base = g_kn + (size_t)bh * DD * SS + s;
        base[(size_t)(2 * lane) * SS]     = tf32r(v2.x * scale);
        base[(size_t)(2 * lane + 1) * SS] = tf32r(v2.y * scale);
    }
}

// ---------------------------------------------------------------------------
// Attention: one CTA = 16 q rows of one (b,h). 16 warps, wide B-frag loads
// with column-permuted mma assignment.
// ---------------------------------------------------------------------------
__global__ void __launch_bounds__(NT, 1)
attn_kernel(float* __restrict__ outp, float* __restrict__ score) {
    extern __shared__ float sm[];
    float* logits = sm + OFF_LOG;
    float* qt     = sm + OFF_QT;
    float* red    = sm + OFF_RED;

    const int t    = threadIdx.x;
    const int lane = t & 31;
    const int warp = t >> 5;     // 0..15
    const int gp   = lane >> 2;  // 0..7
    const int tid4 = lane & 3;   // 0..3

    const int bh = blockIdx.x >> 7;
    const int q0 = (blockIdx.x & 127) * TQ;

    const unsigned* qn = g_qn + (size_t)bh * SS * DD;
    const unsigned* kn = g_kn + (size_t)bh * DD * SS;
    const unsigned* vr = g_vr + (size_t)bh * SS * DD;

    // ---- stage q tile ----
    if (t < 256) {
        int qi = t >> 4, d4 = t & 15;
        uint4 x = *(const uint4*)(qn + (size_t)(q0 + qi) * DD + d4 * 4);
        *(uint4*)((unsigned*)qt + qi * QTS + d4 * 4) = x;
    }
    __syncthreads();

    // ---- A fragments: entire 16x64 Q tile in registers ----
    unsigned a[8][4];
    {
        const unsigned* qtu = (const unsigned*)qt;
        #pragma unroll
        for (int ks = 0; ks < 8; ks++) {
            a[ks][0] = qtu[gp * QTS + ks * 8 + tid4];
            a[ks][1] = qtu[(gp + 8) * QTS + ks * 8 + tid4];
            a[ks][2] = qtu[gp * QTS + ks * 8 + tid4 + 4];
            a[ks][3] = qtu[(gp + 8) * QTS + ks * 8 + tid4 + 4];
        }
    }

    // ========= Phase 1: logits = exp(Q@K^T), wide B loads =====================
    // mma#c in each 32-col group covers columns {gp*4 + c}. C-frag element j of
    // mma#c (frag col tid4*2+j) is actual column (tid4*2+j)*4 + c.
    float ps0 = 0.0f, ps1 = 0.0f;   // row sums for rows gp, gp+8
    {
        const int colbase = warp * 128;
        #pragma unroll
        for (int g = 0; g < 4; g++) {
            const int ng = colbase + g * 32;
            float acc[4][4];
            #pragma unroll
            for (int i = 0; i < 4; i++)
                #pragma unroll
                for (int j = 0; j < 4; j++) acc[i][j] = 0.0f;

            #pragma unroll
            for (int ks = 0; ks < 8; ks++) {
                uint4 f0 = *(const uint4*)(kn + (size_t)(ks * 8 + tid4) * SS + ng + gp * 4);
                uint4 f1 = *(const uint4*)(kn + (size_t)(ks * 8 + 4 + tid4) * SS + ng + gp * 4);
                mma_tf32(acc[0][0], acc[0][1], acc[0][2], acc[0][3],
                         a[ks][0], a[ks][1], a[ks][2], a[ks][3], f0.x, f1.x);
                mma_tf32(acc[1][0], acc[1][1], acc[1][2], acc[1][3],
                         a[ks][0], a[ks][1], a[ks][2], a[ks][3], f0.y, f1.y);
                mma_tf32(acc[2][0], acc[2][1], acc[2][2], acc[2][3],
                         a[ks][0], a[ks][1], a[ks][2], a[ks][3], f0.z, f1.z);
                mma_tf32(acc[3][0], acc[3][1], acc[3][2], acc[3][3],
                         a[ks][0], a[ks][1], a[ks][2], a[ks][3], f0.w, f1.w);
            }

            #pragma unroll
            for (int c = 0; c < 4; c++) {
                float e0 = __expf(acc[c][0]);
                float e1 = __expf(acc[c][1]);
                float e2 = __expf(acc[c][2]);
                float e3 = __expf(acc[c][3]);
                ps0 += e0 + e1;
                ps1 += e2 + e3;
                // actual columns: ng + tid4*8 + c (e0,e2), ng + tid4*8 + 4 + c (e1,e3)
                const int cl = ng + tid4 * 8 + c;
                logits[gp * LSTRIDE + cl]           = e0;
                logits[gp * LSTRIDE + cl + 4]       = e1;
                logits[(gp + 8) * LSTRIDE + cl]     = e2;
                logits[(gp + 8) * LSTRIDE + cl + 4] = e3;
            }
        }
    }

    // ---- row-sum reduction: quad shfl then across 16 warps ----
    ps0 += __shfl_xor_sync(0xffffffffu, ps0, 1);
    ps0 += __shfl_xor_sync(0xffffffffu, ps0, 2);
    ps1 += __shfl_xor_sync(0xffffffffu, ps1, 1);
    ps1 += __shfl_xor_sync(0xffffffffu, ps1, 2);
    float* sums = qt;          // 16 floats (qt dead: frags in regs)
    float* part = qt + 16;     // [16][16]
    __syncthreads();
    if (tid4 == 0) {
        part[warp * 16 + gp]     = ps0;
        part[warp * 16 + 8 + gp] = ps1;
    }
    __syncthreads();
    if (t < 16) {
        float s = 0.0f;
        #pragma unroll
        for (int w = 0; w < 16; w++) s += part[w * 16 + t];
        sums[t] = 1.0f / s;
    }
    __syncthreads();

    // ========= Phase 2: score writes (streaming), coalesced from smem =========
    {
        const int colbase = warp * 128;
        #pragma unroll
        for (int r = 0; r < TQ; r++) {
            float inv = sums[r];
            float4 x = *(const float4*)(logits + (size_t)r * LSTRIDE + colbase + lane * 4);
            x.x *= inv; x.y *= inv; x.z *= inv; x.w *= inv;
            stg_cs4(score + ((size_t)bh * SS + q0 + r) * SS + colbase + lane * 4, x);
        }
    }

    // ========= Phase 3: out = exp(L) @ V, wide V loads =========================
    // mma#c (c=0..3) covers d-cols {gp*4+c}; mma#4+c covers {32+gp*4+c}.
    float acc2[8][4];
    #pragma unroll
    for (int i = 0; i < 8; i++)
        #pragma unroll
        for (int j = 0; j < 4; j++) acc2[i][j] = 0.0f;

    #pragma unroll 4
    for (int ks2 = 0; ks2 < 16; ks2++) {
        const int kgl = warp * 128 + ks2 * 8;
        unsigned a0 = tf32r(logits[gp * LSTRIDE + kgl + tid4]);
        unsigned a1 = tf32r(logits[(gp + 8) * LSTRIDE + kgl + tid4]);
        unsigned a2 = tf32r(logits[gp * LSTRIDE + kgl + tid4 + 4]);
        unsigned a3 = tf32r(logits[(gp + 8) * LSTRIDE + kgl + tid4 + 4]);
        const unsigned* v0 = vr + (size_t)(kgl + tid4) * DD + gp * 4;
        const unsigned* v1 = vr + (size_t)(kgl + 4 + tid4) * DD + gp * 4;
        {
            uint4 g0 = *(const uint4*)v0;
            uint4 g1 = *(const uint4*)v1;
            mma_tf32(acc2[0][0], acc2[0][1], acc2[0][2], acc2[0][3], a0, a1, a2, a3, g0.x, g1.x);
            mma_tf32(acc2[1][0], acc2[1][1], acc2[1][2], acc2[1][3], a0, a1, a2, a3, g0.y, g1.y);
            mma_tf32(acc2[2][0], acc2[2][1], acc2[2][2], acc2[2][3], a0, a1, a2, a3, g0.z, g1.z);
            mma_tf32(acc2[3][0], acc2[3][1], acc2[3][2], acc2[3][3], a0, a1, a2, a3, g0.w, g1.w);
        }
        {
            uint4 h0 = *(const uint4*)(v0 + 32);
            uint4 h1 = *(const uint4*)(v1 + 32);
            mma_tf32(acc2[4][0], acc2[4][1], acc2[4][2], acc2[4][3], a0, a1, a2, a3, h0.x, h1.x);
            mma_tf32(acc2[5][0], acc2[5][1], acc2[5][2], acc2[5][3], a0, a1, a2, a3, h0.y, h1.y);
            mma_tf32(acc2[6][0], acc2[6][1], acc2[6][2], acc2[6][3], a0, a1, a2, a3, h0.z, h1.z);
            mma_tf32(acc2[7][0], acc2[7][1], acc2[7][2], acc2[7][3], a0, a1, a2, a3, h0.w, h1.w);
        }
    }

    // ---- cross-warp reduction (de-permuted d positions) ----
    #pragma unroll
    for (int c = 0; c < 4; c++) {
        // mma#c: d = tid4*8 + c (elems 0,2), tid4*8+4+c (elems 1,3)
        float* m0 = red + warp * (TQ * RTS) + gp * RTS + tid4 * 8 + c;
        m0[0]               = acc2[c][0];
        m0[4]               = acc2[c][1];
        m0[8 * RTS]         = acc2[c][2];
        m0[8 * RTS + 4]     = acc2[c][3];
        // mma#4+c: d = 32 + tid4*8 + c, 32 + tid4*8+4+c
        float* m1 = m0 + 32;
        m1[0]               = acc2[4 + c][0];
        m1[4]               = acc2[4 + c][1];
        m1[8 * RTS]         = acc2[4 + c][2];
        m1[8 * RTS + 4]     = acc2[4 + c][3];
    }
    __syncthreads();
    {
        // 1024 outputs, 512 threads: 2 consecutive d each
        int e  = t * 2;
        int qi = e >> 6;          // 0..15
        int d  = e & 63;
        float2 s2 = make_float2(0.0f, 0.0f);
        #pragma unroll
        for (int w = 0; w < 16; w++) {
            float2 x = *(const float2*)(red + w * (TQ * RTS) + qi * RTS + d);
            s2.x += x.x; s2.y += x.y;
        }
        float inv = sums[qi];
        s2.x *= inv; s2.y *= inv;
        *(float2*)(outp + ((size_t)bh * SS + q0 + qi) * DD + d) = s2;
    }
}

// ---------------------------------------------------------------------------
extern "C" void kernel_launch(void* const* d_in, const int* in_sizes, int n_in,
                              void* d_out, int out_size) {
    const float* q = (const float*)d_in[0];
    const float* k = (const float*)d_in[1];
    const float* v = (const float*)d_in[2];

    float* outp  = (float*)d_out;                 // [B,H,S,D]
    float* score = outp + (size_t)BH * SS * DD;   // [B,H,S,S]

    cudaFuncSetAttribute(attn_kernel,
                         cudaFuncAttributeMaxDynamicSharedMemorySize, SMEM_BYTES);

    prep_kernel<<<(3 * BH * SS) / 8, 256>>>(q, k, v);
    attn_kernel<<<BH * (SS / TQ), NT, SMEM_BYTES>>>(outp, score);
}

// round 10
// speedup vs baseline: 1.8948x; 1.6215x over previous
#include <cuda_runtime.h>
#include <cuda_fp16.h>
#include <cstdint>
#include <math.h>

// Problem shape: q,k,v [2,16,2048,64] fp32
#define BB 2
#define HH 16
#define SS 2048
#define DD 64
#define BH (BB*HH)

#define NT 512          // threads per CTA (16 warps)
#define TQ 16           // q rows per CTA

#define LSC 1028        // logits row stride, u32 cells (2056 halves): 4gp+tid4 banks
#define QSC 36          // q tile stride, u32 cells (72 halves)
#define RTS 68          // reduction row stride (floats)

#define PSCALE 0.0625f  // 2^-4: exp in [e^-10,e^10] -> fp16 normal range
#define UNSCALE 16.0f

// operand layouts (u32 = half2):
// g_qh[bh][s][32]  : q normalized*10, half2 pairs along d
// g_kp[bh][32][s]  : k normalized, cell (dp, s) = half2(K[s][2dp], K[s][2dp+1])
// g_vp[bh][1024][64]: cell (sp, d) = half2(V[2sp][d], V[2sp+1][d])
__device__ unsigned g_qh[(size_t)BH * SS * 32];
__device__ unsigned g_kp[(size_t)BH * 32 * SS];
__device__ unsigned g_vp[(size_t)BH * 1024 * 64];

static __device__ __forceinline__ unsigned packh2(float lo, float hi) {
    __half2 h = __floats2half2_rn(lo, hi);
    return *(unsigned*)&h;
}
static __device__ __forceinline__ float2 unpackh2(unsigned u) {
    return __half22float2(*(__half2*)&u);
}
static __device__ __forceinline__ void mma_f16(float& d0, float& d1, float& d2, float& d3,
                                               unsigned a0, unsigned a1, unsigned a2, unsigned a3,
                                               unsigned b0, unsigned b1) {
    asm volatile(
        "mma.sync.aligned.m16n8k16.row.col.f32.f16.f16.f32 "
        "{%0,%1,%2,%3}, {%4,%5,%6,%7}, {%8,%9}, {%0,%1,%2,%3};"
        : "+f"(d0), "+f"(d1), "+f"(d2), "+f"(d3)
        : "r"(a0), "r"(a1), "r"(a2), "r"(a3), "r"(b0), "r"(b1));
}
static __device__ __forceinline__ void stg_cs4(float* p, float4 v) {
    asm volatile("st.global.cs.v4.f32 [%0], {%1,%2,%3,%4};"
                 :: "l"(p), "f"(v.x), "f"(v.y), "f"(v.z), "f"(v.w) : "memory");
}

// ---------------------------------------------------------------------------
// Prep A: normalize q(x10)/k, pack fp16.
// ---------------------------------------------------------------------------
__global__ void __launch_bounds__(256)
prep_qk(const float* __restrict__ q, const float* __restrict__ k) {
    const int warp = threadIdx.x >> 5;
    const int lane = threadIdx.x & 31;
    const long long id = (long long)blockIdx.x * 8 + warp;
    const long long nrows = (long long)BH * SS;
    const int is_k = (id >= nrows);
    const int row = (int)(is_k ? id - nrows : id);
    const float* src = is_k ? k : q;

    const float2 v2 = ((const float2*)(src + (size_t)row * DD))[lane];
    float ss = v2.x * v2.x + v2.y * v2.y;
    #pragma unroll
    for (int o = 16; o; o >>= 1) ss += __shfl_xor_sync(0xffffffffu, ss, o);
    float scale = 1.0f / fmaxf(sqrtf(ss), 1e-12f);
    if (!is_k) scale *= 10.0f;

    unsigned p = packh2(v2.x * scale, v2.y * scale);
    if (!is_k) {
        g_qh[(size_t)row * 32 + lane] = p;
    } else {
        const int bh = row >> 11, s = row & (SS - 1);
        g_kp[((size_t)bh * 32 + lane) * SS + s] = p;
    }
}

// ---------------------------------------------------------------------------
// Prep B: pack v as half2 pairs along s.
// ---------------------------------------------------------------------------
__global__ void __launch_bounds__(256)
prep_v(const float* __restrict__ v) {
    const int idx = blockIdx.x * 256 + threadIdx.x;  // 0 .. BH*1024*64-1
    const int d  = idx & 63;
    const int sp = (idx >> 6) & 1023;
    const int bh = idx >> 16;
    const float a = v[((size_t)bh * SS + 2 * sp) * DD + d];
    const float b = v[((size_t)bh * SS + 2 * sp + 1) * DD + d];
    g_vp[idx] = packh2(a, b);
}

// ---------------------------------------------------------------------------
// Attention: one CTA = 16 q rows of one (b,h). fp16 mma, all-vectorized L1.
// ---------------------------------------------------------------------------
__global__ void __launch_bounds__(NT, 1)
attn_kernel(float* __restrict__ outp, float* __restrict__ score) {
    extern __shared__ float smf[];
    unsigned* lg  = (unsigned*)smf;          // [16][LSC] u32 (fp16 exp, scaled)
    unsigned* qtu = lg + 16 * LSC;           // [16][QSC]
    float* sums = (float*)(qtu + 16 * QSC);  // [16]
    float* part = sums + 16;                 // [16][16]
    float* red  = part + 256;                // [16][16][RTS]

    const int t    = threadIdx.x;
    const int lane = t & 31;
    const int warp = t >> 5;     // 0..15
    const int gp   = lane >> 2;  // 0..7
    const int tid4 = lane & 3;   // 0..3

    const int bh = blockIdx.x >> 7;
    const int q0 = (blockIdx.x & 127) * TQ;

    const unsigned* qh = g_qh + (size_t)bh * SS * 32;
    const unsigned* kp = g_kp + (size_t)bh * 32 * SS;
    const unsigned* vp = g_vp + (size_t)bh * 1024 * 64;

    // ---- stage q tile (fp16 cells) ----
    if (t < 256) {
        int qi = t >> 4, c2 = t & 15;   // 2 cells each
        uint2 x = *(const uint2*)(qh + (size_t)(q0 + qi) * 32 + c2 * 2);
        *(uint2*)(qtu + qi * QSC + c2 * 2) = x;
    }
    __syncthreads();

    // ---- A fragments: 16x64 Q tile, 4 k-steps x 4 regs ----
    unsigned a[4][4];
    #pragma unroll
    for (int ks = 0; ks < 4; ks++) {
        a[ks][0] = qtu[gp * QSC + ks * 8 + tid4];
        a[ks][1] = qtu[(gp + 8) * QSC + ks * 8 + tid4];
        a[ks][2] = qtu[gp * QSC + ks * 8 + tid4 + 4];
        a[ks][3] = qtu[(gp + 8) * QSC + ks * 8 + tid4 + 4];
    }

    // ========= Phase 1: exp(Q@K^T) -> fp16 smem, fused row sums ==============
    // mma#c covers cols {gp'*4+c}; frag elem j of mma#c -> col tid4*8 + j*4 + c.
    float ps0 = 0.0f, ps1 = 0.0f;
    {
        const int colbase = warp * 128;
        #pragma unroll
        for (int g = 0; g < 4; g++) {
            const int ng = colbase + g * 32;
            float acc[4][4];
            #pragma unroll
            for (int i = 0; i < 4; i++)
                #pragma unroll
                for (int j = 0; j < 4; j++) acc[i][j] = 0.0f;

            #pragma unroll
            for (int ks = 0; ks < 4; ks++) {
                uint4 f0 = *(const uint4*)(kp + (size_t)(ks * 8 + tid4) * SS + ng + gp * 4);
                uint4 f1 = *(const uint4*)(kp + (size_t)(ks * 8 + 4 + tid4) * SS + ng + gp * 4);
                mma_f16(acc[0][0], acc[0][1], acc[0][2], acc[0][3],
                        a[ks][0], a[ks][1], a[ks][2], a[ks][3], f0.x, f1.x);
                mma_f16(acc[1][0], acc[1][1], acc[1][2], acc[1][3],
                        a[ks][0], a[ks][1], a[ks][2], a[ks][3], f0.y, f1.y);
                mma_f16(acc[2][0], acc[2][1], acc[2][2], acc[2][3],
                        a[ks][0], a[ks][1], a[ks][2], a[ks][3], f0.z, f1.z);
                mma_f16(acc[3][0], acc[3][1], acc[3][2], acc[3][3],
                        a[ks][0], a[ks][1], a[ks][2], a[ks][3], f0.w, f1.w);
            }

            float e[4][4];
            #pragma unroll
            for (int c = 0; c < 4; c++) {
                e[c][0] = __expf(acc[c][0]);
                e[c][1] = __expf(acc[c][1]);
                e[c][2] = __expf(acc[c][2]);
                e[c][3] = __expf(acc[c][3]);
                ps0 += e[c][0] + e[c][1];
                ps1 += e[c][2] + e[c][3];
            }
            // rows gp / gp+8, cols ng + tid4*8 + 0..7 -> 2x STS.128 (fp16 scaled)
            const int cell = ng / 2 + tid4 * 4;
            uint4 r0, r1;
            r0.x = packh2(e[0][0] * PSCALE, e[1][0] * PSCALE);
            r0.y = packh2(e[2][0] * PSCALE, e[3][0] * PSCALE);
            r0.z = packh2(e[0][1] * PSCALE, e[1][1] * PSCALE);
            r0.w = packh2(e[2][1] * PSCALE, e[3][1] * PSCALE);
            r1.x = packh2(e[0][2] * PSCALE, e[1][2] * PSCALE);
            r1.y = packh2(e[2][2] * PSCALE, e[3][2] * PSCALE);
            r1.z = packh2(e[0][3] * PSCALE, e[1][3] * PSCALE);
            r1.w = packh2(e[2][3] * PSCALE, e[3][3] * PSCALE);
            *(uint4*)(lg + gp * LSC + cell)       = r0;
            *(uint4*)(lg + (gp + 8) * LSC + cell) = r1;
        }
    }

    // ---- row-sum reduction: quad shfl, then across 16 warps ----
    ps0 += __shfl_xor_sync(0xffffffffu, ps0, 1);
    ps0 += __shfl_xor_sync(0xffffffffu, ps0, 2);
    ps1 += __shfl_xor_sync(0xffffffffu, ps1, 1);
    ps1 += __shfl_xor_sync(0xffffffffu, ps1, 2);
    __syncthreads();
    if (tid4 == 0) {
        part[warp * 16 + gp]     = ps0;
        part[warp * 16 + 8 + gp] = ps1;
    }
    __syncthreads();
    if (t < 16) {
        float s = 0.0f;
        #pragma unroll
        for (int w = 0; w < 16; w++) s += part[w * 16 + t];
        sums[t] = 1.0f / s;
    }
    __syncthreads();

    // ========= Phase 2: score = fp16exp * 16 * inv (streaming stores) =========
    {
        const int colbase = warp * 128;
        #pragma unroll
        for (int r = 0; r < TQ; r++) {
            float inv = sums[r] * UNSCALE;
            uint2 u = *(const uint2*)(lg + (size_t)r * LSC + colbase / 2 + lane * 2);
            float2 x0 = unpackh2(u.x);
            float2 x1 = unpackh2(u.y);
            float4 o = make_float4(x0.x * inv, x0.y * inv, x1.x * inv, x1.y * inv);
            stg_cs4(score + ((size_t)bh * SS + q0 + r) * SS + colbase + lane * 4, o);
        }
    }

    // ========= Phase 3: out = P @ V (fp16 mma), warp owns k-slice 128 ==========
    float acc2[8][4];
    #pragma unroll
    for (int i = 0; i < 8; i++)
        #pragma unroll
        for (int j = 0; j < 4; j++) acc2[i][j] = 0.0f;

    #pragma unroll 2
    for (int ks2 = 0; ks2 < 8; ks2++) {
        const int k0 = warp * 128 + ks2 * 16;     // k offset (halves)
        const int kc = k0 / 2;                    // cell row in vp
        unsigned a0 = lg[gp * LSC + kc + tid4];
        unsigned a1 = lg[(gp + 8) * LSC + kc + tid4];
        unsigned a2 = lg[gp * LSC + kc + tid4 + 4];
        unsigned a3 = lg[(gp + 8) * LSC + kc + tid4 + 4];
        #pragma unroll
        for (int h = 0; h < 2; h++) {
            uint4 g0 = *(const uint4*)(vp + (size_t)(kc + tid4) * 64 + h * 32 + gp * 4);
            uint4 g1 = *(const uint4*)(vp + (size_t)(kc + 4 + tid4) * 64 + h * 32 + gp * 4);
            mma_f16(acc2[h*4+0][0], acc2[h*4+0][1], acc2[h*4+0][2], acc2[h*4+0][3],
                    a0, a1, a2, a3, g0.x, g1.x);
            mma_f16(acc2[h*4+1][0], acc2[h*4+1][1], acc2[h*4+1][2], acc2[h*4+1][3],
                    a0, a1, a2, a3, g0.y, g1.y);
            mma_f16(acc2[h*4+2][0], acc2[h*4+2][1], acc2[h*4+2][2], acc2[h*4+2][3],
                    a0, a1, a2, a3, g0.z, g1.z);
            mma_f16(acc2[h*4+3][0], acc2[h*4+3][1], acc2[h*4+3][2], acc2[h*4+3][3],
                    a0, a1, a2, a3, g0.w, g1.w);
        }
    }

    // ---- cross-warp reduction, vectorized de-permuted stores ----
    #pragma unroll
    for (int h = 0; h < 2; h++) {
        float* m0 = red + warp * (TQ * RTS) + gp * RTS + h * 32 + tid4 * 8;
        *(float4*)m0 = make_float4(acc2[h*4+0][0], acc2[h*4+1][0], acc2[h*4+2][0], acc2[h*4+3][0]);
        *(float4*)(m0 + 4) = make_float4(acc2[h*4+0][1], acc2[h*4+1][1], acc2[h*4+2][1], acc2[h*4+3][1]);
        float* m1 = red + warp * (TQ * RTS) + (gp + 8) * RTS + h * 32 + tid4 * 8;
        *(float4*)m1 = make_float4(acc2[h*4+0][2], acc2[h*4+1][2], acc2[h*4+2][2], acc2[h*4+3][2]);
        *(float4*)(m1 + 4) = make_float4(acc2[h*4+0][3], acc2[h*4+1][3], acc2[h*4+2][3], acc2[h*4+3][3]);
    }
    __syncthreads();
    {
        // 1024 outputs, 512 threads: 2 consecutive d each
        int e  = t * 2;
        int qi = e >> 6;
        int d  = e & 63;
        float2 s2 = make_float2(0.0f, 0.0f);
        #pragma unroll
        for (int w = 0; w < 16; w++) {
            float2 x = *(const float2*)(red + w * (TQ * RTS) + qi * RTS + d);
            s2.x += x.x; s2.y += x.y;
        }
        float inv = sums[qi] * UNSCALE;
        s2.x *= inv; s2.y *= inv;
        *(float2*)(outp + ((size_t)bh * SS + q0 + qi) * DD + d) = s2;
    }
}

#define SMEM_BYTES ((16*LSC + 16*QSC + 16 + 256 + 16*TQ*RTS) * 4)

// ---------------------------------------------------------------------------
extern "C" void kernel_launch(void* const* d_in, const int* in_sizes, int n_in,
                              void* d_out, int out_size) {
    const float* q = (const float*)d_in[0];
    const float* k = (const float*)d_in[1];
    const float* v = (const float*)d_in[2];

    float* outp  = (float*)d_out;                 // [B,H,S,D]
    float* score = outp + (size_t)BH * SS * DD;   // [B,H,S,S]

    cudaFuncSetAttribute(attn_kernel,
                         cudaFuncAttributeMaxDynamicSharedMemorySize, SMEM_BYTES);

    prep_qk<<<(2 * BH * SS) / 8, 256>>>(q, k);
    prep_v<<<(BH * 1024 * 64) / 256, 256>>>(v);
    attn_kernel<<<BH * (SS / TQ), NT, SMEM_BYTES>>>(outp, score);
}

// round 11
// speedup vs baseline: 2.5018x; 1.3203x over previous
#include <cuda_runtime.h>
#include <cuda_fp16.h>
#include <cstdint>
#include <math.h>

// Problem shape: q,k,v [2,16,2048,64] fp32
#define BB 2
#define HH 16
#define SS 2048
#define DD 64
#define BH (BB*HH)

#define NT 512          // threads per CTA (16 warps)
#define TQ 32           // q rows per CTA

#define LSC 1028        // logits row stride, u32 cells: conflict-free P3 scalar LDS
#define QSC 36          // q tile stride, u32 cells
#define RTS 68          // reduction row stride (floats)

// smem layout (float/u32 units)
#define OFF_SUMS 0                      // [32]
#define OFF_PART 32                     // [16][32]
#define OFF_QT   544                    // u32 [32][36] = 1152
#define OFF_LG   1696                   // u32 [32][1028]=32896  OR red fl [16][32][68]=34816
#define SMEM_F   (OFF_LG + 16*TQ*RTS)   // 36512
#define SMEM_BYTES (SMEM_F*4)           // 146048

// operand layouts (u32 = half2):
// g_qh[bh][s][32]   : q normalized * 10*log2(e), half2 pairs along d
// g_kp[bh][32][s]   : cell (dp,s) = half2(K[s][2dp], K[s][2dp+1]) (normalized)
// g_vp[bh][1024][64]: cell (sp,d) = half2(V[2sp][d], V[2sp+1][d])
__device__ unsigned g_qh[(size_t)BH * SS * 32];
__device__ unsigned g_kp[(size_t)BH * 32 * SS];
__device__ unsigned g_vp[(size_t)BH * 1024 * 64];

static __device__ __forceinline__ unsigned packh2(float lo, float hi) {
    __half2 h = __floats2half2_rn(lo, hi);
    return *(unsigned*)&h;
}
static __device__ __forceinline__ float2 unpackh2(unsigned u) {
    return __half22float2(*(__half2*)&u);
}
static __device__ __forceinline__ float ex2(float x) {
    float r; asm("ex2.approx.f32 %0, %1;" : "=f"(r) : "f"(x)); return r;
}
static __device__ __forceinline__ void mma_f16(float& d0, float& d1, float& d2, float& d3,
                                               unsigned a0, unsigned a1, unsigned a2, unsigned a3,
                                               unsigned b0, unsigned b1) {
    asm volatile(
        "mma.sync.aligned.m16n8k16.row.col.f32.f16.f16.f32 "
        "{%0,%1,%2,%3}, {%4,%5,%6,%7}, {%8,%9}, {%0,%1,%2,%3};"
        : "+f"(d0), "+f"(d1), "+f"(d2), "+f"(d3)
        : "r"(a0), "r"(a1), "r"(a2), "r"(a3), "r"(b0), "r"(b1));
}
static __device__ __forceinline__ void stg_cs4(float* p, float4 v) {
    asm volatile("st.global.cs.v4.f32 [%0], {%1,%2,%3,%4};"
                 :: "l"(p), "f"(v.x), "f"(v.y), "f"(v.z), "f"(v.w) : "memory");
}

// ---------------------------------------------------------------------------
// Prep A: normalize q (x10*log2e) / k, pack fp16.
// ---------------------------------------------------------------------------
__global__ void __launch_bounds__(256)
prep_qk(const float* __restrict__ q, const float* __restrict__ k) {
    const int warp = threadIdx.x >> 5;
    const int lane = threadIdx.x & 31;
    const long long id = (long long)blockIdx.x * 8 + warp;
    const long long nrows = (long long)BH * SS;
    const int is_k = (id >= nrows);
    const int row = (int)(is_k ? id - nrows : id);
    const float* src = is_k ? k : q;

    const float2 v2 = ((const float2*)(src + (size_t)row * DD))[lane];
    float ss = v2.x * v2.x + v2.y * v2.y;
    #pragma unroll
    for (int o = 16; o; o >>= 1) ss += __shfl_xor_sync(0xffffffffu, ss, o);
    float scale = 1.0f / fmaxf(sqrtf(ss), 1e-12f);
    if (!is_k) scale *= 14.4269504089f;   // 10 / T folded with log2(e)

    unsigned p = packh2(v2.x * scale, v2.y * scale);
    if (!is_k) {
        g_qh[(size_t)row * 32 + lane] = p;
    } else {
        const int bh = row >> 11, s = row & (SS - 1);
        g_kp[((size_t)bh * 32 + lane) * SS + s] = p;
    }
}

// ---------------------------------------------------------------------------
// Prep B: pack v as half2 pairs along s.
// ---------------------------------------------------------------------------
__global__ void __launch_bounds__(256)
prep_v(const float* __restrict__ v) {
    const int idx = blockIdx.x * 256 + threadIdx.x;
    const int d  = idx & 63;
    const int sp = (idx >> 6) & 1023;
    const int bh = idx >> 16;
    const float a = v[((size_t)bh * SS + 2 * sp) * DD + d];
    const float b = v[((size_t)bh * SS + 2 * sp + 1) * DD + d];
    g_vp[idx] = packh2(a, b);
}

// ---------------------------------------------------------------------------
// Attention: one CTA = 32 q rows of one (b,h). K/V loads feed 2 row-groups.
// ---------------------------------------------------------------------------
__global__ void __launch_bounds__(NT, 1)
attn_kernel(float* __restrict__ outp, float* __restrict__ score) {
    extern __shared__ float smf[];
    float* sums = smf + OFF_SUMS;             // [32]
    float* part = smf + OFF_PART;             // [16][32]
    unsigned* qtu = (unsigned*)(smf + OFF_QT);// [32][QSC]
    unsigned* lg  = (unsigned*)(smf + OFF_LG);// [32][LSC] fp16 exp (log2-dom, -4 bias)
    float* red    = smf + OFF_LG;             // overlays lg after P3 reads

    const int t    = threadIdx.x;
    const int lane = t & 31;
    const int warp = t >> 5;     // 0..15
    const int gp   = lane >> 2;  // 0..7
    const int tid4 = lane & 3;   // 0..3

    const int bh = blockIdx.x >> 6;
    const int q0 = (blockIdx.x & 63) * TQ;

    const unsigned* qh = g_qh + (size_t)bh * SS * 32;
    const unsigned* kp = g_kp + (size_t)bh * 32 * SS;
    const unsigned* vp = g_vp + (size_t)bh * 1024 * 64;

    // ---- stage q tile: 32 rows x 32 cells ----
    {
        int qi = t >> 4, c2 = t & 15;
        uint2 x = *(const uint2*)(qh + (size_t)(q0 + qi) * 32 + c2 * 2);
        *(uint2*)(qtu + qi * QSC + c2 * 2) = x;
    }
    __syncthreads();

    // ---- A fragments: rows 0-15 (aL) and 16-31 (aH) ----
    unsigned aL[4][4], aH[4][4];
    #pragma unroll
    for (int ks = 0; ks < 4; ks++) {
        aL[ks][0] = qtu[gp * QSC + ks * 8 + tid4];
        aL[ks][1] = qtu[(gp + 8) * QSC + ks * 8 + tid4];
        aL[ks][2] = qtu[gp * QSC + ks * 8 + tid4 + 4];
        aL[ks][3] = qtu[(gp + 8) * QSC + ks * 8 + tid4 + 4];
        aH[ks][0] = qtu[(16 + gp) * QSC + ks * 8 + tid4];
        aH[ks][1] = qtu[(24 + gp) * QSC + ks * 8 + tid4];
        aH[ks][2] = qtu[(16 + gp) * QSC + ks * 8 + tid4 + 4];
        aH[ks][3] = qtu[(24 + gp) * QSC + ks * 8 + tid4 + 4];
    }

    // ========= Phase 1: 2^(Q@K^T - 4) -> fp16 smem, fused row sums ===========
    // logits already in log2 domain (log2e folded into q); acc init -4 = scale.
    float ps0 = 0.f, ps1 = 0.f, ps2 = 0.f, ps3 = 0.f;
    {
        const int colbase = warp * 128;
        #pragma unroll
        for (int g = 0; g < 4; g++) {
            const int ng = colbase + g * 32;
            float A[4][4], B[4][4];
            #pragma unroll
            for (int i = 0; i < 4; i++)
                #pragma unroll
                for (int j = 0; j < 4; j++) { A[i][j] = -4.0f; B[i][j] = -4.0f; }

            #pragma unroll
            for (int ks = 0; ks < 4; ks++) {
                uint4 f0 = *(const uint4*)(kp + (size_t)(ks * 8 + tid4) * SS + ng + gp * 4);
                uint4 f1 = *(const uint4*)(kp + (size_t)(ks * 8 + 4 + tid4) * SS + ng + gp * 4);
                mma_f16(A[0][0],A[0][1],A[0][2],A[0][3], aL[ks][0],aL[ks][1],aL[ks][2],aL[ks][3], f0.x,f1.x);
                mma_f16(A[1][0],A[1][1],A[1][2],A[1][3], aL[ks][0],aL[ks][1],aL[ks][2],aL[ks][3], f0.y,f1.y);
                mma_f16(A[2][0],A[2][1],A[2][2],A[2][3], aL[ks][0],aL[ks][1],aL[ks][2],aL[ks][3], f0.z,f1.z);
                mma_f16(A[3][0],A[3][1],A[3][2],A[3][3], aL[ks][0],aL[ks][1],aL[ks][2],aL[ks][3], f0.w,f1.w);
                mma_f16(B[0][0],B[0][1],B[0][2],B[0][3], aH[ks][0],aH[ks][1],aH[ks][2],aH[ks][3], f0.x,f1.x);
                mma_f16(B[1][0],B[1][1],B[1][2],B[1][3], aH[ks][0],aH[ks][1],aH[ks][2],aH[ks][3], f0.y,f1.y);
                mma_f16(B[2][0],B[2][1],B[2][2],B[2][3], aH[ks][0],aH[ks][1],aH[ks][2],aH[ks][3], f0.z,f1.z);
                mma_f16(B[3][0],B[3][1],B[3][2],B[3][3], aH[ks][0],aH[ks][1],aH[ks][2],aH[ks][3], f0.w,f1.w);
            }

            float eA[4][4], eB[4][4];
            #pragma unroll
            for (int c = 0; c < 4; c++) {
                eA[c][0] = ex2(A[c][0]); eA[c][1] = ex2(A[c][1]);
                eA[c][2] = ex2(A[c][2]); eA[c][3] = ex2(A[c][3]);
                eB[c][0] = ex2(B[c][0]); eB[c][1] = ex2(B[c][1]);
                eB[c][2] = ex2(B[c][2]); eB[c][3] = ex2(B[c][3]);
                ps0 += eA[c][0] + eA[c][1];
                ps1 += eA[c][2] + eA[c][3];
                ps2 += eB[c][0] + eB[c][1];
                ps3 += eB[c][2] + eB[c][3];
            }
            const int cell = ng / 2 + tid4 * 4;
            uint4 r0, r1, r2, r3;
            r0.x = packh2(eA[0][0], eA[1][0]); r0.y = packh2(eA[2][0], eA[3][0]);
            r0.z = packh2(eA[0][1], eA[1][1]); r0.w = packh2(eA[2][1], eA[3][1]);
            r1.x = packh2(eA[0][2], eA[1][2]); r1.y = packh2(eA[2][2], eA[3][2]);
            r1.z = packh2(eA[0][3], eA[1][3]); r1.w = packh2(eA[2][3], eA[3][3]);
            r2.x = packh2(eB[0][0], eB[1][0]); r2.y = packh2(eB[2][0], eB[3][0]);
            r2.z = packh2(eB[0][1], eB[1][1]); r2.w = packh2(eB[2][1], eB[3][1]);
            r3.x = packh2(eB[0][2], eB[1][2]); r3.y = packh2(eB[2][2], eB[3][2]);
            r3.z = packh2(eB[0][3], eB[1][3]); r3.w = packh2(eB[2][3], eB[3][3]);
            *(uint4*)(lg + gp * LSC + cell)        = r0;
            *(uint4*)(lg + (gp + 8) * LSC + cell)  = r1;
            *(uint4*)(lg + (16 + gp) * LSC + cell) = r2;
            *(uint4*)(lg + (24 + gp) * LSC + cell) = r3;
        }
    }

    // ---- row-sum reduction: quad shfl, then across 16 warps ----
    ps0 += __shfl_xor_sync(0xffffffffu, ps0, 1);
    ps0 += __shfl_xor_sync(0xffffffffu, ps0, 2);
    ps1 += __shfl_xor_sync(0xffffffffu, ps1, 1);
    ps1 += __shfl_xor_sync(0xffffffffu, ps1, 2);
    ps2 += __shfl_xor_sync(0xffffffffu, ps2, 1);
    ps2 += __shfl_xor_sync(0xffffffffu, ps2, 2);
    ps3 += __shfl_xor_sync(0xffffffffu, ps3, 1);
    ps3 += __shfl_xor_sync(0xffffffffu, ps3, 2);
    __syncthreads();
    if (tid4 == 0) {
        part[warp * 32 + gp]      = ps0;
        part[warp * 32 + 8 + gp]  = ps1;
        part[warp * 32 + 16 + gp] = ps2;
        part[warp * 32 + 24 + gp] = ps3;
    }
    __syncthreads();
    if (t < 32) {
        float s = 0.0f;
        #pragma unroll
        for (int w = 0; w < 16; w++) s += part[w * 32 + t];
        sums[t] = 1.0f / s;
    }
    __syncthreads();

    // ========= Phase 2: score = exp16 * inv (streaming), warp's col-slice =====
    {
        const int colbase = warp * 128;
        #pragma unroll 8
        for (int r = 0; r < TQ; r++) {
            float inv = sums[r];
            uint2 u = *(const uint2*)(lg + (size_t)r * LSC + colbase / 2 + lane * 2);
            float2 x0 = unpackh2(u.x);
            float2 x1 = unpackh2(u.y);
            float4 o = make_float4(x0.x * inv, x0.y * inv, x1.x * inv, x1.y * inv);
            stg_cs4(score + ((size_t)bh * SS + q0 + r) * SS + colbase + lane * 4, o);
        }
    }

    // ========= Phase 3: out = P @ V, V loads feed both row-groups =============
    float cA[8][4], cB[8][4];
    #pragma unroll
    for (int i = 0; i < 8; i++)
        #pragma unroll
        for (int j = 0; j < 4; j++) { cA[i][j] = 0.0f; cB[i][j] = 0.0f; }

    #pragma unroll 2
    for (int ks2 = 0; ks2 < 8; ks2++) {
        const int kc = warp * 64 + ks2 * 8;   // cell row (k/2)
        unsigned l0 = lg[gp * LSC + kc + tid4];
        unsigned l1 = lg[(gp + 8) * LSC + kc + tid4];
        unsigned l2 = lg[gp * LSC + kc + tid4 + 4];
        unsigned l3 = lg[(gp + 8) * LSC + kc + tid4 + 4];
        unsigned h0 = lg[(16 + gp) * LSC + kc + tid4];
        unsigned h1 = lg[(24 + gp) * LSC + kc + tid4];
        unsigned h2 = lg[(16 + gp) * LSC + kc + tid4 + 4];
        unsigned h3 = lg[(24 + gp) * LSC + kc + tid4 + 4];
        #pragma unroll
        for (int h = 0; h < 2; h++) {
            uint4 g0 = *(const uint4*)(vp + (size_t)(kc + tid4) * 64 + h * 32 + gp * 4);
            uint4 g1 = *(const uint4*)(vp + (size_t)(kc + 4 + tid4) * 64 + h * 32 + gp * 4);
            mma_f16(cA[h*4+0][0],cA[h*4+0][1],cA[h*4+0][2],cA[h*4+0][3], l0,l1,l2,l3, g0.x,g1.x);
            mma_f16(cA[h*4+1][0],cA[h*4+1][1],cA[h*4+1][2],cA[h*4+1][3], l0,l1,l2,l3, g0.y,g1.y);
            mma_f16(cA[h*4+2][0],cA[h*4+2][1],cA[h*4+2][2],cA[h*4+2][3], l0,l1,l2,l3, g0.z,g1.z);
            mma_f16(cA[h*4+3][0],cA[h*4+3][1],cA[h*4+3][2],cA[h*4+3][3], l0,l1,l2,l3, g0.w,g1.w);
            mma_f16(cB[h*4+0][0],cB[h*4+0][1],cB[h*4+0][2],cB[h*4+0][3], h0,h1,h2,h3, g0.x,g1.x);
            mma_f16(cB[h*4+1][0],cB[h*4+1][1],cB[h*4+1][2],cB[h*4+1][3], h0,h1,h2,h3, g0.y,g1.y);
            mma_f16(cB[h*4+2][0],cB[h*4+2][1],cB[h*4+2][2],cB[h*4+2][3], h0,h1,h2,h3, g0.z,g1.z);
            mma_f16(cB[h*4+3][0],cB[h*4+3][1],cB[h*4+3][2],cB[h*4+3][3], h0,h1,h2,h3, g0.w,g1.w);
        }
    }
    __syncthreads();   // all lg reads done before red overlays it

    // ---- cross-warp reduction (red overlays lg) ----
    {
        float* base = red + warp * (TQ * RTS);
        #pragma unroll
        for (int h = 0; h < 2; h++) {
            float* m0 = base + gp * RTS + h * 32 + tid4 * 8;
            *(float4*)m0       = make_float4(cA[h*4+0][0], cA[h*4+1][0], cA[h*4+2][0], cA[h*4+3][0]);
            *(float4*)(m0 + 4) = make_float4(cA[h*4+0][1], cA[h*4+1][1], cA[h*4+2][1], cA[h*4+3][1]);
            float* m1 = base + (gp + 8) * RTS + h * 32 + tid4 * 8;
            *(float4*)m1       = make_float4(cA[h*4+0][2], cA[h*4+1][2], cA[h*4+2][2], cA[h*4+3][2]);
            *(float4*)(m1 + 4) = make_float4(cA[h*4+0][3], cA[h*4+1][3], cA[h*4+2][3], cA[h*4+3][3]);
            float* m2 = base + (16 + gp) * RTS + h * 32 + tid4 * 8;
            *(float4*)m2       = make_float4(cB[h*4+0][0], cB[h*4+1][0], cB[h*4+2][0], cB[h*4+3][0]);
            *(float4*)(m2 + 4) = make_float4(cB[h*4+0][1], cB[h*4+1][1], cB[h*4+2][1], cB[h*4+3][1]);
            float* m3 = base + (24 + gp) * RTS + h * 32 + tid4 * 8;
            *(float4*)m3       = make_float4(cB[h*4+0][2], cB[h*4+1][2], cB[h*4+2][2], cB[h*4+3][2]);
            *(float4*)(m3 + 4) = make_float4(cB[h*4+0][3], cB[h*4+1][3], cB[h*4+2][3], cB[h*4+3][3]);
        }
    }
    __syncthreads();
    {
        // 2048 outputs, 512 threads: float4 each
        int qi = t >> 4;          // 0..31
        int d0 = (t & 15) * 4;
        float4 s4 = make_float4(0, 0, 0, 0);
        #pragma unroll
        for (int w = 0; w < 16; w++) {
            float4 x = *(const float4*)(red + w * (TQ * RTS) + qi * RTS + d0);
            s4.x += x.x; s4.y += x.y; s4.z += x.z; s4.w += x.w;
        }
        float inv = sums[qi];
        s4.x *= inv; s4.y *= inv; s4.z *= inv; s4.w *= inv;
        *(float4*)(outp + ((size_t)bh * SS + q0 + qi) * DD + d0) = s4;
    }
}

// ---------------------------------------------------------------------------
extern "C" void kernel_launch(void* const* d_in, const int* in_sizes, int n_in,
                              void* d_out, int out_size) {
    const float* q = (const float*)d_in[0];
    const float* k = (const float*)d_in[1];
    const float* v = (const float*)d_in[2];

    float* outp  = (float*)d_out;                 // [B,H,S,D]
    float* score = outp + (size_t)BH * SS * DD;   // [B,H,S,S]

    cudaFuncSetAttribute(attn_kernel,
                         cudaFuncAttributeMaxDynamicSharedMemorySize, SMEM_BYTES);

    prep_qk<<<(2 * BH * SS) / 8, 256>>>(q, k);
    prep_v<<<(BH * 1024 * 64) / 256, 256>>>(v);
    attn_kernel<<<BH * (SS / TQ), NT, SMEM_BYTES>>>(outp, score);
}

// round 12
// speedup vs baseline: 2.7963x; 1.1177x over previous
#include <cuda_runtime.h>
#include <cuda_fp16.h>
#include <cstdint>
#include <math.h>

// Problem shape: q,k,v [2,16,2048,64] fp32
#define BB 2
#define HH 16
#define SS 2048
#define DD 64
#define BH (BB*HH)

#define NT 512          // threads per CTA (16 warps)
#define TQ 32           // q rows per CTA

#define LSC 1028        // logits row stride, u32 cells
#define QSC 36          // q tile stride, u32 cells
#define RTS 68          // reduction row stride (floats)

// smem layout (float/u32 units)
#define OFF_SUMS 0                      // [32]
#define OFF_PART 32                     // [16][32]
#define OFF_QT   544                    // u32 [32][36]
#define OFF_LG   1696                   // u32 [32][1028] OR red [16][32][68]
#define SMEM_F   (OFF_LG + 16*TQ*RTS)
#define SMEM_BYTES (SMEM_F*4)           // 146048

// operand layouts (u32 = half2):
// g_qh[bh][s][32]   : q normalized * (10*log2e), half2 pairs along d
// g_kp[bh][32][s]   : cell (dp,s) = half2(K[s][2dp], K[s][2dp+1]) (normalized)
// g_vp[bh][1024][64]: cell (sp,d) = half2(V[2sp][d], V[2sp+1][d])
__device__ unsigned g_qh[(size_t)BH * SS * 32];
__device__ unsigned g_kp[(size_t)BH * 32 * SS];
__device__ unsigned g_vp[(size_t)BH * 1024 * 64];

static __device__ __forceinline__ unsigned packh2(float lo, float hi) {
    __half2 h = __floats2half2_rn(lo, hi);
    return *(unsigned*)&h;
}
static __device__ __forceinline__ float2 unpackh2(unsigned u) {
    return __half22float2(*(__half2*)&u);
}
static __device__ __forceinline__ float ex2(float x) {
    float r; asm("ex2.approx.f32 %0, %1;" : "=f"(r) : "f"(x)); return r;
}
static __device__ __forceinline__ void mma_f16(float& d0, float& d1, float& d2, float& d3,
                                               unsigned a0, unsigned a1, unsigned a2, unsigned a3,
                                               unsigned b0, unsigned b1) {
    asm volatile(
        "mma.sync.aligned.m16n8k16.row.col.f32.f16.f16.f32 "
        "{%0,%1,%2,%3}, {%4,%5,%6,%7}, {%8,%9}, {%0,%1,%2,%3};"
        : "+f"(d0), "+f"(d1), "+f"(d2), "+f"(d3)
        : "r"(a0), "r"(a1), "r"(a2), "r"(a3), "r"(b0), "r"(b1));
}
static __device__ __forceinline__ void stg_cs4(float* p, float4 v) {
    asm volatile("st.global.cs.v4.f32 [%0], {%1,%2,%3,%4};"
                 :: "l"(p), "f"(v.x), "f"(v.y), "f"(v.z), "f"(v.w) : "memory");
}

#define QK_BLOCKS 4096   // 131072 q+k rows / 32 rows per block
#define V_BLOCKS  1024   // 2M v cells / (256 thr * 8 cells)

// ---------------------------------------------------------------------------
// Merged prep: q/k normalize+pack (4 rows/warp, 8 LDG in flight) and v pack
// (8 cells/thread, 4 LDG.128 in flight).
// ---------------------------------------------------------------------------
__global__ void __launch_bounds__(256)
prep_all(const float* __restrict__ q, const float* __restrict__ k,
         const float* __restrict__ v) {
    const int b = blockIdx.x;
    if (b < QK_BLOCKS) {
        const int warp = threadIdx.x >> 5;
        const int lane = threadIdx.x & 31;
        const int lrow = lane >> 3;          // 0..3: row within warp
        const int l8   = lane & 7;           // 0..7: lane within row
        const int rid  = b * 32 + warp * 4 + lrow;   // 0..131071
        const int is_k = rid >= BH * SS;
        const int row  = is_k ? rid - BH * SS : rid;
        const float* src = is_k ? k : q;

        const float4* rp = (const float4*)(src + (size_t)row * DD);
        float4 x0 = rp[l8 * 2];
        float4 x1 = rp[l8 * 2 + 1];
        float ss = x0.x*x0.x + x0.y*x0.y + x0.z*x0.z + x0.w*x0.w
                 + x1.x*x1.x + x1.y*x1.y + x1.z*x1.z + x1.w*x1.w;
        ss += __shfl_xor_sync(0xffffffffu, ss, 1);
        ss += __shfl_xor_sync(0xffffffffu, ss, 2);
        ss += __shfl_xor_sync(0xffffffffu, ss, 4);
        float scale = 1.0f / fmaxf(sqrtf(ss), 1e-12f);
        if (!is_k) scale *= 14.4269504089f;   // (1/T) * log2(e)

        unsigned c0 = packh2(x0.x * scale, x0.y * scale);
        unsigned c1 = packh2(x0.z * scale, x0.w * scale);
        unsigned c2 = packh2(x1.x * scale, x1.y * scale);
        unsigned c3 = packh2(x1.z * scale, x1.w * scale);
        if (!is_k) {
            *(uint4*)(g_qh + (size_t)row * 32 + l8 * 4) = make_uint4(c0, c1, c2, c3);
        } else {
            const int bh = row >> 11, s = row & (SS - 1);
            unsigned* base = g_kp + ((size_t)bh * 32 + l8 * 4) * SS + s;
            base[0]      = c0;
            base[SS]     = c1;
            base[2 * SS] = c2;
            base[3 * SS] = c3;
        }
    } else {
        // v: 8 cells per thread = 2 sp-chunks x 4 d
        const int idx = (b - QK_BLOCKS) * 256 + threadIdx.x;   // 0..262143
        const int d0  = (idx & 15) * 4;
        const int sp0 = ((idx >> 4) & 511) * 2;
        const int bh  = idx >> 13;
        const float* vb = v + (size_t)bh * SS * DD;
        float4 a0 = *(const float4*)(vb + (size_t)(2 * sp0) * DD + d0);
        float4 b0 = *(const float4*)(vb + (size_t)(2 * sp0 + 1) * DD + d0);
        float4 a1 = *(const float4*)(vb + (size_t)(2 * sp0 + 2) * DD + d0);
        float4 b1 = *(const float4*)(vb + (size_t)(2 * sp0 + 3) * DD + d0);
        unsigned* dst = g_vp + ((size_t)bh * 1024 + sp0) * 64 + d0;
        *(uint4*)dst = make_uint4(packh2(a0.x, b0.x), packh2(a0.y, b0.y),
                                  packh2(a0.z, b0.z), packh2(a0.w, b0.w));
        *(uint4*)(dst + 64) = make_uint4(packh2(a1.x, b1.x), packh2(a1.y, b1.y),
                                         packh2(a1.z, b1.z), packh2(a1.w, b1.w));
    }
}

// ---------------------------------------------------------------------------
// Attention: one CTA = 32 q rows of one (b,h).
// ---------------------------------------------------------------------------
__global__ void __launch_bounds__(NT, 1)
attn_kernel(float* __restrict__ outp, float* __restrict__ score) {
    extern __shared__ float smf[];
    float* sums = smf + OFF_SUMS;
    float* part = smf + OFF_PART;
    unsigned* qtu = (unsigned*)(smf + OFF_QT);
    unsigned* lg  = (unsigned*)(smf + OFF_LG);
    float* red    = smf + OFF_LG;

    const int t    = threadIdx.x;
    const int lane = t & 31;
    const int warp = t >> 5;
    const int gp   = lane >> 2;
    const int tid4 = lane & 3;

    const int bh = blockIdx.x >> 6;
    const int q0 = (blockIdx.x & 63) * TQ;

    const unsigned* qh = g_qh + (size_t)bh * SS * 32;
    const unsigned* kp = g_kp + (size_t)bh * 32 * SS;
    const unsigned* vp = g_vp + (size_t)bh * 1024 * 64;

    // ---- stage q tile ----
    {
        int qi = t >> 4, c2 = t & 15;
        uint2 x = *(const uint2*)(qh + (size_t)(q0 + qi) * 32 + c2 * 2);
        *(uint2*)(qtu + qi * QSC + c2 * 2) = x;
    }
    __syncthreads();

    // ---- A fragments: rows 0-15 (aL) and 16-31 (aH) ----
    unsigned aL[4][4], aH[4][4];
    #pragma unroll
    for (int ks = 0; ks < 4; ks++) {
        aL[ks][0] = qtu[gp * QSC + ks * 8 + tid4];
        aL[ks][1] = qtu[(gp + 8) * QSC + ks * 8 + tid4];
        aL[ks][2] = qtu[gp * QSC + ks * 8 + tid4 + 4];
        aL[ks][3] = qtu[(gp + 8) * QSC + ks * 8 + tid4 + 4];
        aH[ks][0] = qtu[(16 + gp) * QSC + ks * 8 + tid4];
        aH[ks][1] = qtu[(24 + gp) * QSC + ks * 8 + tid4];
        aH[ks][2] = qtu[(16 + gp) * QSC + ks * 8 + tid4 + 4];
        aH[ks][3] = qtu[(24 + gp) * QSC + ks * 8 + tid4 + 4];
    }

    // ========= Phase 1: 2^(Q@K^T - 4) -> fp16 smem, fused row sums ===========
    float ps0 = 0.f, ps1 = 0.f, ps2 = 0.f, ps3 = 0.f;
    {
        const int colbase = warp * 128;
        #pragma unroll
        for (int g = 0; g < 4; g++) {
            const int ng = colbase + g * 32;
            float A[4][4], B[4][4];
            #pragma unroll
            for (int i = 0; i < 4; i++)
                #pragma unroll
                for (int j = 0; j < 4; j++) { A[i][j] = -4.0f; B[i][j] = -4.0f; }

            #pragma unroll
            for (int ks = 0; ks < 4; ks++) {
                uint4 f0 = *(const uint4*)(kp + (size_t)(ks * 8 + tid4) * SS + ng + gp * 4);
                uint4 f1 = *(const uint4*)(kp + (size_t)(ks * 8 + 4 + tid4) * SS + ng + gp * 4);
                mma_f16(A[0][0],A[0][1],A[0][2],A[0][3], aL[ks][0],aL[ks][1],aL[ks][2],aL[ks][3], f0.x,f1.x);
                mma_f16(A[1][0],A[1][1],A[1][2],A[1][3], aL[ks][0],aL[ks][1],aL[ks][2],aL[ks][3], f0.y,f1.y);
                mma_f16(A[2][0],A[2][1],A[2][2],A[2][3], aL[ks][0],aL[ks][1],aL[ks][2],aL[ks][3], f0.z,f1.z);
                mma_f16(A[3][0],A[3][1],A[3][2],A[3][3], aL[ks][0],aL[ks][1],aL[ks][2],aL[ks][3], f0.w,f1.w);
                mma_f16(B[0][0],B[0][1],B[0][2],B[0][3], aH[ks][0],aH[ks][1],aH[ks][2],aH[ks][3], f0.x,f1.x);
                mma_f16(B[1][0],B[1][1],B[1][2],B[1][3], aH[ks][0],aH[ks][1],aH[ks][2],aH[ks][3], f0.y,f1.y);
                mma_f16(B[2][0],B[2][1],B[2][2],B[2][3], aH[ks][0],aH[ks][1],aH[ks][2],aH[ks][3], f0.z,f1.z);
                mma_f16(B[3][0],B[3][1],B[3][2],B[3][3], aH[ks][0],aH[ks][1],aH[ks][2],aH[ks][3], f0.w,f1.w);
            }

            float eA[4][4], eB[4][4];
            #pragma unroll
            for (int c = 0; c < 4; c++) {
                eA[c][0] = ex2(A[c][0]); eA[c][1] = ex2(A[c][1]);
                eA[c][2] = ex2(A[c][2]); eA[c][3] = ex2(A[c][3]);
                eB[c][0] = ex2(B[c][0]); eB[c][1] = ex2(B[c][1]);
                eB[c][2] = ex2(B[c][2]); eB[c][3] = ex2(B[c][3]);
                ps0 += eA[c][0] + eA[c][1];
                ps1 += eA[c][2] + eA[c][3];
                ps2 += eB[c][0] + eB[c][1];
                ps3 += eB[c][2] + eB[c][3];
            }
            const int cell = ng / 2 + tid4 * 4;
            uint4 r0, r1, r2, r3;
            r0.x = packh2(eA[0][0], eA[1][0]); r0.y = packh2(eA[2][0], eA[3][0]);
            r0.z = packh2(eA[0][1], eA[1][1]); r0.w = packh2(eA[2][1], eA[3][1]);
            r1.x = packh2(eA[0][2], eA[1][2]); r1.y = packh2(eA[2][2], eA[3][2]);
            r1.z = packh2(eA[0][3], eA[1][3]); r1.w = packh2(eA[2][3], eA[3][3]);
            r2.x = packh2(eB[0][0], eB[1][0]); r2.y = packh2(eB[2][0], eB[3][0]);
            r2.z = packh2(eB[0][1], eB[1][1]); r2.w = packh2(eB[2][1], eB[3][1]);
            r3.x = packh2(eB[0][2], eB[1][2]); r3.y = packh2(eB[2][2], eB[3][2]);
            r3.z = packh2(eB[0][3], eB[1][3]); r3.w = packh2(eB[2][3], eB[3][3]);
            *(uint4*)(lg + gp * LSC + cell)        = r0;
            *(uint4*)(lg + (gp + 8) * LSC + cell)  = r1;
            *(uint4*)(lg + (16 + gp) * LSC + cell) = r2;
            *(uint4*)(lg + (24 + gp) * LSC + cell) = r3;
        }
    }

    // ---- row-sum reduction ----
    ps0 += __shfl_xor_sync(0xffffffffu, ps0, 1);
    ps0 += __shfl_xor_sync(0xffffffffu, ps0, 2);
    ps1 += __shfl_xor_sync(0xffffffffu, ps1, 1);
    ps1 += __shfl_xor_sync(0xffffffffu, ps1, 2);
    ps2 += __shfl_xor_sync(0xffffffffu, ps2, 1);
    ps2 += __shfl_xor_sync(0xffffffffu, ps2, 2);
    ps3 += __shfl_xor_sync(0xffffffffu, ps3, 1);
    ps3 += __shfl_xor_sync(0xffffffffu, ps3, 2);
    __syncthreads();
    if (tid4 == 0) {
        part[warp * 32 + gp]      = ps0;
        part[warp * 32 + 8 + gp]  = ps1;
        part[warp * 32 + 16 + gp] = ps2;
        part[warp * 32 + 24 + gp] = ps3;
    }
    __syncthreads();
    if (t < 32) {
        float s = 0.0f;
        #pragma unroll
        for (int w = 0; w < 16; w++) s += part[w * 32 + t];
        sums[t] = 1.0f / s;
    }
    __syncthreads();

    // ========= Phase 2+3 fused: per-iteration V prefetch + score STG + mma ===
    float cA[8][4], cB[8][4];
    #pragma unroll
    for (int i = 0; i < 8; i++)
        #pragma unroll
        for (int j = 0; j < 4; j++) { cA[i][j] = 0.0f; cB[i][j] = 0.0f; }

    const int colbase = warp * 128;
    #pragma unroll
    for (int ks2 = 0; ks2 < 8; ks2++) {
        const int kc = warp * 64 + ks2 * 8;   // cell row (k/2)

        // ---- V prefetch (4 LDG.128, used by mma below) ----
        uint4 g0 = *(const uint4*)(vp + (size_t)(kc + tid4) * 64 + gp * 4);
        uint4 g1 = *(const uint4*)(vp + (size_t)(kc + 4 + tid4) * 64 + gp * 4);
        uint4 h0g = *(const uint4*)(vp + (size_t)(kc + tid4) * 64 + 32 + gp * 4);
        uint4 h1g = *(const uint4*)(vp + (size_t)(kc + 4 + tid4) * 64 + 32 + gp * 4);

        // ---- score STG for rows 4*ks2 .. 4*ks2+3 (overlaps V latency) ----
        #pragma unroll
        for (int rr = 0; rr < 4; rr++) {
            const int r = ks2 * 4 + rr;
            float inv = sums[r];
            uint2 u = *(const uint2*)(lg + (size_t)r * LSC + colbase / 2 + lane * 2);
            float2 x0 = unpackh2(u.x);
            float2 x1 = unpackh2(u.y);
            float4 o = make_float4(x0.x * inv, x0.y * inv, x1.x * inv, x1.y * inv);
            stg_cs4(score + ((size_t)bh * SS + q0 + r) * SS + colbase + lane * 4, o);
        }

        // ---- P A-fragments from lg ----
        unsigned l0 = lg[gp * LSC + kc + tid4];
        unsigned l1 = lg[(gp + 8) * LSC + kc + tid4];
        unsigned l2 = lg[gp * LSC + kc + tid4 + 4];
        unsigned l3 = lg[(gp + 8) * LSC + kc + tid4 + 4];
        unsigned h0 = lg[(16 + gp) * LSC + kc + tid4];
        unsigned h1 = lg[(24 + gp) * LSC + kc + tid4];
        unsigned h2 = lg[(16 + gp) * LSC + kc + tid4 + 4];
        unsigned h3 = lg[(24 + gp) * LSC + kc + tid4 + 4];

        mma_f16(cA[0][0],cA[0][1],cA[0][2],cA[0][3], l0,l1,l2,l3, g0.x,g1.x);
        mma_f16(cA[1][0],cA[1][1],cA[1][2],cA[1][3], l0,l1,l2,l3, g0.y,g1.y);
        mma_f16(cA[2][0],cA[2][1],cA[2][2],cA[2][3], l0,l1,l2,l3, g0.z,g1.z);
        mma_f16(cA[3][0],cA[3][1],cA[3][2],cA[3][3], l0,l1,l2,l3, g0.w,g1.w);
        mma_f16(cA[4][0],cA[4][1],cA[4][2],cA[4][3], l0,l1,l2,l3, h0g.x,h1g.x);
        mma_f16(cA[5][0],cA[5][1],cA[5][2],cA[5][3], l0,l1,l2,l3, h0g.y,h1g.y);
        mma_f16(cA[6][0],cA[6][1],cA[6][2],cA[6][3], l0,l1,l2,l3, h0g.z,h1g.z);
        mma_f16(cA[7][0],cA[7][1],cA[7][2],cA[7][3], l0,l1,l2,l3, h0g.w,h1g.w);
        mma_f16(cB[0][0],cB[0][1],cB[0][2],cB[0][3], h0,h1,h2,h3, g0.x,g1.x);
        mma_f16(cB[1][0],cB[1][1],cB[1][2],cB[1][3], h0,h1,h2,h3, g0.y,g1.y);
        mma_f16(cB[2][0],cB[2][1],cB[2][2],cB[2][3], h0,h1,h2,h3, g0.z,g1.z);
        mma_f16(cB[3][0],cB[3][1],cB[3][2],cB[3][3], h0,h1,h2,h3, g0.w,g1.w);
        mma_f16(cB[4][0],cB[4][1],cB[4][2],cB[4][3], h0,h1,h2,h3, h0g.x,h1g.x);
        mma_f16(cB[5][0],cB[5][1],cB[5][2],cB[5][3], h0,h1,h2,h3, h0g.y,h1g.y);
        mma_f16(cB[6][0],cB[6][1],cB[6][2],cB[6][3], h0,h1,h2,h3, h0g.z,h1g.z);
        mma_f16(cB[7][0],cB[7][1],cB[7][2],cB[7][3], h0,h1,h2,h3, h0g.w,h1g.w);
    }
    __syncthreads();   // all lg reads done before red overlays it

    // ---- cross-warp reduction (red overlays lg) ----
    {
        float* base = red + warp * (TQ * RTS);
        #pragma unroll
        for (int h = 0; h < 2; h++) {
            float* m0 = base + gp * RTS + h * 32 + tid4 * 8;
            *(float4*)m0       = make_float4(cA[h*4+0][0], cA[h*4+1][0], cA[h*4+2][0], cA[h*4+3][0]);
            *(float4*)(m0 + 4) = make_float4(cA[h*4+0][1], cA[h*4+1][1], cA[h*4+2][1], cA[h*4+3][1]);
            float* m1 = base + (gp + 8) * RTS + h * 32 + tid4 * 8;
            *(float4*)m1       = make_float4(cA[h*4+0][2], cA[h*4+1][2], cA[h*4+2][2], cA[h*4+3][2]);
            *(float4*)(m1 + 4) = make_float4(cA[h*4+0][3], cA[h*4+1][3], cA[h*4+2][3], cA[h*4+3][3]);
            float* m2 = base + (16 + gp) * RTS + h * 32 + tid4 * 8;
            *(float4*)m2       = make_float4(cB[h*4+0][0], cB[h*4+1][0], cB[h*4+2][0], cB[h*4+3][0]);
            *(float4*)(m2 + 4) = make_float4(cB[h*4+0][1], cB[h*4+1][1], cB[h*4+2][1], cB[h*4+3][1]);
            float* m3 = base + (24 + gp) * RTS + h * 32 + tid4 * 8;
            *(float4*)m3       = make_float4(cB[h*4+0][2], cB[h*4+1][2], cB[h*4+2][2], cB[h*4+3][2]);
            *(float4*)(m3 + 4) = make_float4(cB[h*4+0][3], cB[h*4+1][3], cB[h*4+2][3], cB[h*4+3][3]);
        }
    }
    __syncthreads();
    {
        int qi = t >> 4;
        int d0 = (t & 15) * 4;
        float4 s4 = make_float4(0, 0, 0, 0);
        #pragma unroll
        for (int w = 0; w < 16; w++) {
            float4 x = *(const float4*)(red + w * (TQ * RTS) + qi * RTS + d0);
            s4.x += x.x; s4.y += x.y; s4.z += x.z; s4.w += x.w;
        }
        float inv = sums[qi];
        s4.x *= inv; s4.y *= inv; s4.z *= inv; s4.w *= inv;
        *(float4*)(outp + ((size_t)bh * SS + q0 + qi) * DD + d0) = s4;
    }
}

// ---------------------------------------------------------------------------
extern "C" void kernel_launch(void* const* d_in, const int* in_sizes, int n_in,
                              void* d_out, int out_size) {
    const float* q = (const float*)d_in[0];
    const float* k = (const float*)d_in[1];
    const float* v = (const float*)d_in[2];

    float* outp  = (float*)d_out;                 // [B,H,S,D]
    float* score = outp + (size_t)BH * SS * DD;   // [B,H,S,S]

    cudaFuncSetAttribute(attn_kernel,
                         cudaFuncAttributeMaxDynamicSharedMemorySize, SMEM_BYTES);

    prep_all<<<QK_BLOCKS + V_BLOCKS, 256>>>(q, k, v);
    attn_kernel<<<BH * (SS / TQ), NT, SMEM_BYTES>>>(outp, score);
}

// round 13
// speedup vs baseline: 2.8564x; 1.0215x over previous
#include <cuda_runtime.h>
#include <cuda_fp16.h>
#include <cstdint>
#include <math.h>

// Problem shape: q,k,v [2,16,2048,64] fp32
#define BB 2
#define HH 16
#define SS 2048
#define DD 64
#define BH (BB*HH)

#define NT 512          // threads per CTA (16 warps)
#define TQ 32           // q rows per CTA

#define LSC 1028        // logits row stride, u32 cells
#define QSC 36          // q tile stride, u32 cells
#define RCS 48          // red row stride, u32 cells (fp16 pairs): conflict-free

// smem layout (float/u32 units)
#define OFF_SUMS 0                      // [32]
#define OFF_PART 32                     // [16][32]
#define OFF_QT   544                    // u32 [32][36]
#define OFF_LG   1696                   // u32 [32][1028] OR red u32 [16][32][48]
#define SMEM_F   (OFF_LG + TQ*LSC)
#define SMEM_BYTES (SMEM_F*4)           // 146048

// operand layouts (u32 = half2):
__device__ unsigned g_qh[(size_t)BH * SS * 32];
__device__ unsigned g_kp[(size_t)BH * 32 * SS];
__device__ unsigned g_vp[(size_t)BH * 1024 * 64];

static __device__ __forceinline__ unsigned packh2(float lo, float hi) {
    __half2 h = __floats2half2_rn(lo, hi);
    return *(unsigned*)&h;
}
static __device__ __forceinline__ float2 unpackh2(unsigned u) {
    return __half22float2(*(__half2*)&u);
}
static __device__ __forceinline__ float ex2(float x) {
    float r; asm("ex2.approx.f32 %0, %1;" : "=f"(r) : "f"(x)); return r;
}
static __device__ __forceinline__ void mma_f16(float& d0, float& d1, float& d2, float& d3,
                                               unsigned a0, unsigned a1, unsigned a2, unsigned a3,
                                               unsigned b0, unsigned b1) {
    asm volatile(
        "mma.sync.aligned.m16n8k16.row.col.f32.f16.f16.f32 "
        "{%0,%1,%2,%3}, {%4,%5,%6,%7}, {%8,%9}, {%0,%1,%2,%3};"
        : "+f"(d0), "+f"(d1), "+f"(d2), "+f"(d3)
        : "r"(a0), "r"(a1), "r"(a2), "r"(a3), "r"(b0), "r"(b1));
}
static __device__ __forceinline__ void stg_cs4(float* p, float4 v) {
    asm volatile("st.global.cs.v4.f32 [%0], {%1,%2,%3,%4};"
                 :: "l"(p), "f"(v.x), "f"(v.y), "f"(v.z), "f"(v.w) : "memory");
}

#define QK_BLOCKS 4096
#define V_BLOCKS  1024

// ---------------------------------------------------------------------------
// Merged prep (unchanged from R9: ~5us)
// ---------------------------------------------------------------------------
__global__ void __launch_bounds__(256)
prep_all(const float* __restrict__ q, const float* __restrict__ k,
         const float* __restrict__ v) {
    const int b = blockIdx.x;
    if (b < QK_BLOCKS) {
        const int warp = threadIdx.x >> 5;
        const int lane = threadIdx.x & 31;
        const int lrow = lane >> 3;
        const int l8   = lane & 7;
        const int rid  = b * 32 + warp * 4 + lrow;
        const int is_k = rid >= BH * SS;
        const int row  = is_k ? rid - BH * SS : rid;
        const float* src = is_k ? k : q;

        const float4* rp = (const float4*)(src + (size_t)row * DD);
        float4 x0 = rp[l8 * 2];
        float4 x1 = rp[l8 * 2 + 1];
        float ss = x0.x*x0.x + x0.y*x0.y + x0.z*x0.z + x0.w*x0.w
                 + x1.x*x1.x + x1.y*x1.y + x1.z*x1.z + x1.w*x1.w;
        ss += __shfl_xor_sync(0xffffffffu, ss, 1);
        ss += __shfl_xor_sync(0xffffffffu, ss, 2);
        ss += __shfl_xor_sync(0xffffffffu, ss, 4);
        float scale = 1.0f / fmaxf(sqrtf(ss), 1e-12f);
        if (!is_k) scale *= 14.4269504089f;   // (1/T) * log2(e)

        unsigned c0 = packh2(x0.x * scale, x0.y * scale);
        unsigned c1 = packh2(x0.z * scale, x0.w * scale);
        unsigned c2 = packh2(x1.x * scale, x1.y * scale);
        unsigned c3 = packh2(x1.z * scale, x1.w * scale);
        if (!is_k) {
            *(uint4*)(g_qh + (size_t)row * 32 + l8 * 4) = make_uint4(c0, c1, c2, c3);
        } else {
            const int bh = row >> 11, s = row & (SS - 1);
            unsigned* base = g_kp + ((size_t)bh * 32 + l8 * 4) * SS + s;
            base[0]      = c0;
            base[SS]     = c1;
            base[2 * SS] = c2;
            base[3 * SS] = c3;
        }
    } else {
        const int idx = (b - QK_BLOCKS) * 256 + threadIdx.x;
        const int d0  = (idx & 15) * 4;
        const int sp0 = ((idx >> 4) & 511) * 2;
        const int bh  = idx >> 13;
        const float* vb = v + (size_t)bh * SS * DD;
        float4 a0 = *(const float4*)(vb + (size_t)(2 * sp0) * DD + d0);
        float4 b0 = *(const float4*)(vb + (size_t)(2 * sp0 + 1) * DD + d0);
        float4 a1 = *(const float4*)(vb + (size_t)(2 * sp0 + 2) * DD + d0);
        float4 b1 = *(const float4*)(vb + (size_t)(2 * sp0 + 3) * DD + d0);
        unsigned* dst = g_vp + ((size_t)bh * 1024 + sp0) * 64 + d0;
        *(uint4*)dst = make_uint4(packh2(a0.x, b0.x), packh2(a0.y, b0.y),
                                  packh2(a0.z, b0.z), packh2(a0.w, b0.w));
        *(uint4*)(dst + 64) = make_uint4(packh2(a1.x, b1.x), packh2(a1.y, b1.y),
                                         packh2(a1.z, b1.z), packh2(a1.w, b1.w));
    }
}

// ---------------------------------------------------------------------------
// Attention: one CTA = 32 q rows of one (b,h).
// ---------------------------------------------------------------------------
__global__ void __launch_bounds__(NT, 1)
attn_kernel(float* __restrict__ outp, float* __restrict__ score) {
    extern __shared__ float smf[];
    float* sums = smf + OFF_SUMS;
    float* part = smf + OFF_PART;
    unsigned* qtu  = (unsigned*)(smf + OFF_QT);
    unsigned* lg   = (unsigned*)(smf + OFF_LG);
    unsigned* redu = (unsigned*)(smf + OFF_LG);   // overlays lg after P3

    const int t    = threadIdx.x;
    const int lane = t & 31;
    const int warp = t >> 5;
    const int gp   = lane >> 2;
    const int tid4 = lane & 3;

    const int bh = blockIdx.x >> 6;
    const int q0 = (blockIdx.x & 63) * TQ;

    const unsigned* qh = g_qh + (size_t)bh * SS * 32;
    const unsigned* kp = g_kp + (size_t)bh * 32 * SS;
    const unsigned* vp = g_vp + (size_t)bh * 1024 * 64;

    // ---- stage q tile ----
    {
        int qi = t >> 4, c2 = t & 15;
        uint2 x = *(const uint2*)(qh + (size_t)(q0 + qi) * 32 + c2 * 2);
        *(uint2*)(qtu + qi * QSC + c2 * 2) = x;
    }
    __syncthreads();

    // ---- A fragments: rows 0-15 (aL) and 16-31 (aH) ----
    unsigned aL[4][4], aH[4][4];
    #pragma unroll
    for (int ks = 0; ks < 4; ks++) {
        aL[ks][0] = qtu[gp * QSC + ks * 8 + tid4];
        aL[ks][1] = qtu[(gp + 8) * QSC + ks * 8 + tid4];
        aL[ks][2] = qtu[gp * QSC + ks * 8 + tid4 + 4];
        aL[ks][3] = qtu[(gp + 8) * QSC + ks * 8 + tid4 + 4];
        aH[ks][0] = qtu[(16 + gp) * QSC + ks * 8 + tid4];
        aH[ks][1] = qtu[(24 + gp) * QSC + ks * 8 + tid4];
        aH[ks][2] = qtu[(16 + gp) * QSC + ks * 8 + tid4 + 4];
        aH[ks][3] = qtu[(24 + gp) * QSC + ks * 8 + tid4 + 4];
    }

    // ========= Phase 1: 2^(Q@K^T - 4) -> fp16 smem, fused row sums ===========
    float ps0 = 0.f, ps1 = 0.f, ps2 = 0.f, ps3 = 0.f;
    {
        const int colbase = warp * 128;
        #pragma unroll
        for (int g = 0; g < 4; g++) {
            const int ng = colbase + g * 32;
            float A[4][4], B[4][4];
            #pragma unroll
            for (int i = 0; i < 4; i++)
                #pragma unroll
                for (int j = 0; j < 4; j++) { A[i][j] = -4.0f; B[i][j] = -4.0f; }

            #pragma unroll
            for (int ks = 0; ks < 4; ks++) {
                uint4 f0 = *(const uint4*)(kp + (size_t)(ks * 8 + tid4) * SS + ng + gp * 4);
                uint4 f1 = *(const uint4*)(kp + (size_t)(ks * 8 + 4 + tid4) * SS + ng + gp * 4);
                mma_f16(A[0][0],A[0][1],A[0][2],A[0][3], aL[ks][0],aL[ks][1],aL[ks][2],aL[ks][3], f0.x,f1.x);
                mma_f16(A[1][0],A[1][1],A[1][2],A[1][3], aL[ks][0],aL[ks][1],aL[ks][2],aL[ks][3], f0.y,f1.y);
                mma_f16(A[2][0],A[2][1],A[2][2],A[2][3], aL[ks][0],aL[ks][1],aL[ks][2],aL[ks][3], f0.z,f1.z);
                mma_f16(A[3][0],A[3][1],A[3][2],A[3][3], aL[ks][0],aL[ks][1],aL[ks][2],aL[ks][3], f0.w,f1.w);
                mma_f16(B[0][0],B[0][1],B[0][2],B[0][3], aH[ks][0],aH[ks][1],aH[ks][2],aH[ks][3], f0.x,f1.x);
                mma_f16(B[1][0],B[1][1],B[1][2],B[1][3], aH[ks][0],aH[ks][1],aH[ks][2],aH[ks][3], f0.y,f1.y);
                mma_f16(B[2][0],B[2][1],B[2][2],B[2][3], aH[ks][0],aH[ks][1],aH[ks][2],aH[ks][3], f0.z,f1.z);
                mma_f16(B[3][0],B[3][1],B[3][2],B[3][3], aH[ks][0],aH[ks][1],aH[ks][2],aH[ks][3], f0.w,f1.w);
            }

            float eA[4][4], eB[4][4];
            #pragma unroll
            for (int c = 0; c < 4; c++) {
                eA[c][0] = ex2(A[c][0]); eA[c][1] = ex2(A[c][1]);
                eA[c][2] = ex2(A[c][2]); eA[c][3] = ex2(A[c][3]);
                eB[c][0] = ex2(B[c][0]); eB[c][1] = ex2(B[c][1]);
                eB[c][2] = ex2(B[c][2]); eB[c][3] = ex2(B[c][3]);
                ps0 += eA[c][0] + eA[c][1];
                ps1 += eA[c][2] + eA[c][3];
                ps2 += eB[c][0] + eB[c][1];
                ps3 += eB[c][2] + eB[c][3];
            }
            const int cell = ng / 2 + tid4 * 4;
            uint4 r0, r1, r2, r3;
            r0.x = packh2(eA[0][0], eA[1][0]); r0.y = packh2(eA[2][0], eA[3][0]);
            r0.z = packh2(eA[0][1], eA[1][1]); r0.w = packh2(eA[2][1], eA[3][1]);
            r1.x = packh2(eA[0][2], eA[1][2]); r1.y = packh2(eA[2][2], eA[3][2]);
            r1.z = packh2(eA[0][3], eA[1][3]); r1.w = packh2(eA[2][3], eA[3][3]);
            r2.x = packh2(eB[0][0], eB[1][0]); r2.y = packh2(eB[2][0], eB[3][0]);
            r2.z = packh2(eB[0][1], eB[1][1]); r2.w = packh2(eB[2][1], eB[3][1]);
            r3.x = packh2(eB[0][2], eB[1][2]); r3.y = packh2(eB[2][2], eB[3][2]);
            r3.z = packh2(eB[0][3], eB[1][3]); r3.w = packh2(eB[2][3], eB[3][3]);
            *(uint4*)(lg + gp * LSC + cell)        = r0;
            *(uint4*)(lg + (gp + 8) * LSC + cell)  = r1;
            *(uint4*)(lg + (16 + gp) * LSC + cell) = r2;
            *(uint4*)(lg + (24 + gp) * LSC + cell) = r3;
        }
    }

    // ---- prefetch V for iter 0 (independent of smem/syncs) ----
    uint4 vg0, vg1, vh0, vh1;
    {
        const int kc = warp * 64;
        vg0 = *(const uint4*)(vp + (size_t)(kc + tid4) * 64 + gp * 4);
        vg1 = *(const uint4*)(vp + (size_t)(kc + 4 + tid4) * 64 + gp * 4);
        vh0 = *(const uint4*)(vp + (size_t)(kc + tid4) * 64 + 32 + gp * 4);
        vh1 = *(const uint4*)(vp + (size_t)(kc + 4 + tid4) * 64 + 32 + gp * 4);
    }

    // ---- row-sum reduction ----
    ps0 += __shfl_xor_sync(0xffffffffu, ps0, 1);
    ps0 += __shfl_xor_sync(0xffffffffu, ps0, 2);
    ps1 += __shfl_xor_sync(0xffffffffu, ps1, 1);
    ps1 += __shfl_xor_sync(0xffffffffu, ps1, 2);
    ps2 += __shfl_xor_sync(0xffffffffu, ps2, 1);
    ps2 += __shfl_xor_sync(0xffffffffu, ps2, 2);
    ps3 += __shfl_xor_sync(0xffffffffu, ps3, 1);
    ps3 += __shfl_xor_sync(0xffffffffu, ps3, 2);
    __syncthreads();
    if (tid4 == 0) {
        part[warp * 32 + gp]      = ps0;
        part[warp * 32 + 8 + gp]  = ps1;
        part[warp * 32 + 16 + gp] = ps2;
        part[warp * 32 + 24 + gp] = ps3;
    }
    __syncthreads();
    if (t < 32) {
        float s = 0.0f;
        #pragma unroll
        for (int w = 0; w < 16; w++) s += part[w * 32 + t];
        sums[t] = 1.0f / s;
    }
    __syncthreads();

    // ========= Phase 2+3 fused: V pipelined, score STG overlapped with mma ===
    float cA[8][4], cB[8][4];
    #pragma unroll
    for (int i = 0; i < 8; i++)
        #pragma unroll
        for (int j = 0; j < 4; j++) { cA[i][j] = 0.0f; cB[i][j] = 0.0f; }

    const int colbase = warp * 128;
    #pragma unroll
    for (int ks2 = 0; ks2 < 8; ks2++) {
        const int kc = warp * 64 + ks2 * 8;

        // ---- prefetch V for next iter ----
        uint4 ng0, ng1, nh0, nh1;
        if (ks2 < 7) {
            const int nkc = kc + 8;
            ng0 = *(const uint4*)(vp + (size_t)(nkc + tid4) * 64 + gp * 4);
            ng1 = *(const uint4*)(vp + (size_t)(nkc + 4 + tid4) * 64 + gp * 4);
            nh0 = *(const uint4*)(vp + (size_t)(nkc + tid4) * 64 + 32 + gp * 4);
            nh1 = *(const uint4*)(vp + (size_t)(nkc + 4 + tid4) * 64 + 32 + gp * 4);
        }

        // ---- score STG for rows 4*ks2 .. 4*ks2+3 ----
        #pragma unroll
        for (int rr = 0; rr < 4; rr++) {
            const int r = ks2 * 4 + rr;
            float inv = sums[r];
            uint2 u = *(const uint2*)(lg + (size_t)r * LSC + colbase / 2 + lane * 2);
            float2 x0 = unpackh2(u.x);
            float2 x1 = unpackh2(u.y);
            float4 o = make_float4(x0.x * inv, x0.y * inv, x1.x * inv, x1.y * inv);
            stg_cs4(score + ((size_t)bh * SS + q0 + r) * SS + colbase + lane * 4, o);
        }

        // ---- P A-fragments from lg ----
        unsigned l0 = lg[gp * LSC + kc + tid4];
        unsigned l1 = lg[(gp + 8) * LSC + kc + tid4];
        unsigned l2 = lg[gp * LSC + kc + tid4 + 4];
        unsigned l3 = lg[(gp + 8) * LSC + kc + tid4 + 4];
        unsigned h0 = lg[(16 + gp) * LSC + kc + tid4];
        unsigned h1 = lg[(24 + gp) * LSC + kc + tid4];
        unsigned h2 = lg[(16 + gp) * LSC + kc + tid4 + 4];
        unsigned h3 = lg[(24 + gp) * LSC + kc + tid4 + 4];

        mma_f16(cA[0][0],cA[0][1],cA[0][2],cA[0][3], l0,l1,l2,l3, vg0.x,vg1.x);
        mma_f16(cA[1][0],cA[1][1],cA[1][2],cA[1][3], l0,l1,l2,l3, vg0.y,vg1.y);
        mma_f16(cA[2][0],cA[2][1],cA[2][2],cA[2][3], l0,l1,l2,l3, vg0.z,vg1.z);
        mma_f16(cA[3][0],cA[3][1],cA[3][2],cA[3][3], l0,l1,l2,l3, vg0.w,vg1.w);
        mma_f16(cA[4][0],cA[4][1],cA[4][2],cA[4][3], l0,l1,l2,l3, vh0.x,vh1.x);
        mma_f16(cA[5][0],cA[5][1],cA[5][2],cA[5][3], l0,l1,l2,l3, vh0.y,vh1.y);
        mma_f16(cA[6][0],cA[6][1],cA[6][2],cA[6][3], l0,l1,l2,l3, vh0.z,vh1.z);
        mma_f16(cA[7][0],cA[7][1],cA[7][2],cA[7][3], l0,l1,l2,l3, vh0.w,vh1.w);
        mma_f16(cB[0][0],cB[0][1],cB[0][2],cB[0][3], h0,h1,h2,h3, vg0.x,vg1.x);
        mma_f16(cB[1][0],cB[1][1],cB[1][2],cB[1][3], h0,h1,h2,h3, vg0.y,vg1.y);
        mma_f16(cB[2][0],cB[2][1],cB[2][2],cB[2][3], h0,h1,h2,h3, vg0.z,vg1.z);
        mma_f16(cB[3][0],cB[3][1],cB[3][2],cB[3][3], h0,h1,h2,h3, vg0.w,vg1.w);
        mma_f16(cB[4][0],cB[4][1],cB[4][2],cB[4][3], h0,h1,h2,h3, vh0.x,vh1.x);
        mma_f16(cB[5][0],cB[5][1],cB[5][2],cB[5][3], h0,h1,h2,h3, vh0.y,vh1.y);
        mma_f16(cB[6][0],cB[6][1],cB[6][2],cB[6][3], h0,h1,h2,h3, vh0.z,vh1.z);
        mma_f16(cB[7][0],cB[7][1],cB[7][2],cB[7][3], h0,h1,h2,h3, vh0.w,vh1.w);

        if (ks2 < 7) { vg0 = ng0; vg1 = ng1; vh0 = nh0; vh1 = nh1; }
    }
    __syncthreads();   // all lg reads done before red overlays it

    // ---- cross-warp reduction: fp16 packed (x 1/16), conflict-free RCS=48 ----
    {
        unsigned* base = redu + warp * (TQ * RCS);
        #pragma unroll
        for (int h = 0; h < 2; h++) {
            const int cell = h * 16 + tid4 * 4;
            // rows gp, gp+8 (cA), gp+16, gp+24 (cB); pack (c, c+1) pairs = adjacent d
            uint4 r0, r1, r2, r3;
            r0.x = packh2(cA[h*4+0][0]*0.0625f, cA[h*4+1][0]*0.0625f);
            r0.y = packh2(cA[h*4+2][0]*0.0625f, cA[h*4+3][0]*0.0625f);
            r0.z = packh2(cA[h*4+0][1]*0.0625f, cA[h*4+1][1]*0.0625f);
            r0.w = packh2(cA[h*4+2][1]*0.0625f, cA[h*4+3][1]*0.0625f);
            r1.x = packh2(cA[h*4+0][2]*0.0625f, cA[h*4+1][2]*0.0625f);
            r1.y = packh2(cA[h*4+2][2]*0.0625f, cA[h*4+3][2]*0.0625f);
            r1.z = packh2(cA[h*4+0][3]*0.0625f, cA[h*4+1][3]*0.0625f);
            r1.w = packh2(cA[h*4+2][3]*0.0625f, cA[h*4+3][3]*0.0625f);
            r2.x = packh2(cB[h*4+0][0]*0.0625f, cB[h*4+1][0]*0.0625f);
            r2.y = packh2(cB[h*4+2][0]*0.0625f, cB[h*4+3][0]*0.0625f);
            r2.z = packh2(cB[h*4+0][1]*0.0625f, cB[h*4+1][1]*0.0625f);
            r2.w = packh2(cB[h*4+2][1]*0.0625f, cB[h*4+3][1]*0.0625f);
            r3.x = packh2(cB[h*4+0][2]*0.0625f, cB[h*4+1][2]*0.0625f);
            r3.y = packh2(cB[h*4+2][2]*0.0625f, cB[h*4+3][2]*0.0625f);
            r3.z = packh2(cB[h*4+0][3]*0.0625f, cB[h*4+1][3]*0.0625f);
            r3.w = packh2(cB[h*4+2][3]*0.0625f, cB[h*4+3][3]*0.0625f);
            *(uint4*)(base + gp * RCS + cell)        = r0;
            *(uint4*)(base + (gp + 8) * RCS + cell)  = r1;
            *(uint4*)(base + (16 + gp) * RCS + cell) = r2;
            *(uint4*)(base + (24 + gp) * RCS + cell) = r3;
        }
    }
    __syncthreads();
    {
        // 2048 outputs, 512 threads: 4 d each via uint2 (2 fp16 cells)
        int qi = t >> 4;
        int c2 = (t & 15) * 2;      // cell base; d0 = 2*c2
        float4 s4 = make_float4(0, 0, 0, 0);
        #pragma unroll
        for (int w = 0; w < 16; w++) {
            uint2 u = *(const uint2*)(redu + w * (TQ * RCS) + qi * RCS + c2);
            float2 p0 = unpackh2(u.x);
            float2 p1 = unpackh2(u.y);
            s4.x += p0.x; s4.y += p0.y; s4.z += p1.x; s4.w += p1.y;
        }
        float inv = sums[qi] * 16.0f;
        s4.x *= inv; s4.y *= inv; s4.z *= inv; s4.w *= inv;
        *(float4*)(outp + ((size_t)bh * SS + q0 + qi) * DD + c2 * 2) = s4;
    }
}

// ---------------------------------------------------------------------------
extern "C" void kernel_launch(void* const* d_in, const int* in_sizes, int n_in,
                              void* d_out, int out_size) {
    const float* q = (const float*)d_in[0];
    const float* k = (const float*)d_in[1];
    const float* v = (const float*)d_in[2];

    float* outp  = (float*)d_out;                 // [B,H,S,D]
    float* score = outp + (size_t)BH * SS * DD;   // [B,H,S,S]

    cudaFuncSetAttribute(attn_kernel,
                         cudaFuncAttributeMaxDynamicSharedMemorySize, SMEM_BYTES);

    prep_all<<<QK_BLOCKS + V_BLOCKS, 256>>>(q, k, v);
    attn_kernel<<<BH * (SS / TQ), NT, SMEM_BYTES>>>(outp, score);
}

// round 16
// speedup vs baseline: 2.8879x; 1.0110x over previous
#include <cuda_runtime.h>
#include <cuda_fp16.h>
#include <cstdint>
#include <math.h>

// Problem shape: q,k,v [2,16,2048,64] fp32
#define BB 2
#define HH 16
#define SS 2048
#define DD 64
#define BH (BB*HH)

#define NT 512          // threads per CTA (16 warps)
#define TQ 32           // q rows per CTA

#define LSC 1036        // logits row stride, u32 cells (== 12 mod 32: STS ~conflict-free, P3 LDS conflict-free)
#define QSC 36          // q tile stride, u32 cells
#define RCS 48          // red row stride, u32 cells (fp16 pairs): conflict-free

// smem layout (float/u32 units)
#define OFF_SUMS 0                      // [32]
#define OFF_PART 32                     // [16][32]
#define OFF_QT   544                    // u32 [32][36]
#define OFF_LG   1696                   // u32 [32][1036] OR red u32 [16][32][48]
#define SMEM_F   (OFF_LG + TQ*LSC)
#define SMEM_BYTES (SMEM_F*4)           // 139392

// operand layouts (u32 = half2):
__device__ unsigned g_qh[(size_t)BH * SS * 32];
__device__ unsigned g_kp[(size_t)BH * 32 * SS];
__device__ unsigned g_vp[(size_t)BH * 1024 * 64];

static __device__ __forceinline__ unsigned packh2(float lo, float hi) {
    __half2 h = __floats2half2_rn(lo, hi);
    return *(unsigned*)&h;
}
static __device__ __forceinline__ float2 unpackh2(unsigned u) {
    return __half22float2(*(__half2*)&u);
}
static __device__ __forceinline__ float ex2(float x) {
    float r; asm("ex2.approx.f32 %0, %1;" : "=f"(r) : "f"(x)); return r;
}
static __device__ __forceinline__ void mma_f16(float& d0, float& d1, float& d2, float& d3,
                                               unsigned a0, unsigned a1, unsigned a2, unsigned a3,
                                               unsigned b0, unsigned b1) {
    asm volatile(
        "mma.sync.aligned.m16n8k16.row.col.f32.f16.f16.f32 "
        "{%0,%1,%2,%3}, {%4,%5,%6,%7}, {%8,%9}, {%0,%1,%2,%3};"
        : "+f"(d0), "+f"(d1), "+f"(d2), "+f"(d3)
        : "r"(a0), "r"(a1), "r"(a2), "r"(a3), "r"(b0), "r"(b1));
}
static __device__ __forceinline__ void stg_cs4(float* p, float4 v) {
    asm volatile("st.global.cs.v4.f32 [%0], {%1,%2,%3,%4};"
                 :: "l"(p), "f"(v.x), "f"(v.y), "f"(v.z), "f"(v.w) : "memory");
}

#define QK_BLOCKS 4096
#define V_BLOCKS  1024

// ---------------------------------------------------------------------------
// Merged prep (~5us)
// ---------------------------------------------------------------------------
__global__ void __launch_bounds__(256)
prep_all(const float* __restrict__ q, const float* __restrict__ k,
         const float* __restrict__ v) {
    const int b = blockIdx.x;
    if (b < QK_BLOCKS) {
        const int warp = threadIdx.x >> 5;
        const int lane = threadIdx.x & 31;
        const int lrow = lane >> 3;
        const int l8   = lane & 7;
        const int rid  = b * 32 + warp * 4 + lrow;
        const int is_k = rid >= BH * SS;
        const int row  = is_k ? rid - BH * SS : rid;
        const float* src = is_k ? k : q;

        const float4* rp = (const float4*)(src + (size_t)row * DD);
        float4 x0 = rp[l8 * 2];
        float4 x1 = rp[l8 * 2 + 1];
        float ss = x0.x*x0.x + x0.y*x0.y + x0.z*x0.z + x0.w*x0.w
                 + x1.x*x1.x + x1.y*x1.y + x1.z*x1.z + x1.w*x1.w;
        ss += __shfl_xor_sync(0xffffffffu, ss, 1);
        ss += __shfl_xor_sync(0xffffffffu, ss, 2);
        ss += __shfl_xor_sync(0xffffffffu, ss, 4);
        float scale = 1.0f / fmaxf(sqrtf(ss), 1e-12f);
        if (!is_k) scale *= 14.4269504089f;   // (1/T) * log2(e)

        unsigned c0 = packh2(x0.x * scale, x0.y * scale);
        unsigned c1 = packh2(x0.z * scale, x0.w * scale);
        unsigned c2 = packh2(x1.x * scale, x1.y * scale);
        unsigned c3 = packh2(x1.z * scale, x1.w * scale);
        if (!is_k) {
            *(uint4*)(g_qh + (size_t)row * 32 + l8 * 4) = make_uint4(c0, c1, c2, c3);
        } else {
            const int bh = row >> 11, s = row & (SS - 1);
            unsigned* base = g_kp + ((size_t)bh * 32 + l8 * 4) * SS + s;
            base[0]      = c0;
            base[SS]     = c1;
            base[2 * SS] = c2;
            base[3 * SS] = c3;
        }
    } else {
        const int idx = (b - QK_BLOCKS) * 256 + threadIdx.x;
        const int d0  = (idx & 15) * 4;
        const int sp0 = ((idx >> 4) & 511) * 2;
        const int bh  = idx >> 13;
        const float* vb = v + (size_t)bh * SS * DD;
        float4 a0 = *(const float4*)(vb + (size_t)(2 * sp0) * DD + d0);
        float4 b0 = *(const float4*)(vb + (size_t)(2 * sp0 + 1) * DD + d0);
        float4 a1 = *(const float4*)(vb + (size_t)(2 * sp0 + 2) * DD + d0);
        float4 b1 = *(const float4*)(vb + (size_t)(2 * sp0 + 3) * DD + d0);
        unsigned* dst = g_vp + ((size_t)bh * 1024 + sp0) * 64 + d0;
        *(uint4*)dst = make_uint4(packh2(a0.x, b0.x), packh2(a0.y, b0.y),
                                  packh2(a0.z, b0.z), packh2(a0.w, b0.w));
        *(uint4*)(dst + 64) = make_uint4(packh2(a1.x, b1.x), packh2(a1.y, b1.y),
                                         packh2(a1.z, b1.z), packh2(a1.w, b1.w));
    }
}

// ---------------------------------------------------------------------------
// Attention: one CTA = 32 q rows of one (b,h).
// ---------------------------------------------------------------------------
__global__ void __launch_bounds__(NT, 1)
attn_kernel(float* __restrict__ outp, float* __restrict__ score) {
    extern __shared__ float smf[];
    float* sums = smf + OFF_SUMS;
    float* part = smf + OFF_PART;
    unsigned* qtu  = (unsigned*)(smf + OFF_QT);
    unsigned* lg   = (unsigned*)(smf + OFF_LG);
    unsigned* redu = (unsigned*)(smf + OFF_LG);   // overlays lg after P3

    const int t    = threadIdx.x;
    const int lane = t & 31;
    const int warp = t >> 5;
    const int gp   = lane >> 2;
    const int tid4 = lane & 3;

    const int bh = blockIdx.x >> 6;
    const int q0 = (blockIdx.x & 63) * TQ;

    const unsigned* qh = g_qh + (size_t)bh * SS * 32;
    const unsigned* kp = g_kp + (size_t)bh * 32 * SS;
    const unsigned* vp = g_vp + (size_t)bh * 1024 * 64;

    // ---- stage q tile ----
    {
        int qi = t >> 4, c2 = t & 15;
        uint2 x = *(const uint2*)(qh + (size_t)(q0 + qi) * 32 + c2 * 2);
        *(uint2*)(qtu + qi * QSC + c2 * 2) = x;
    }
    __syncthreads();

    // ---- A fragments: rows 0-15 (aL) and 16-31 (aH) ----
    unsigned aL[4][4], aH[4][4];
    #pragma unroll
    for (int ks = 0; ks < 4; ks++) {
        aL[ks][0] = qtu[gp * QSC + ks * 8 + tid4];
        aL[ks][1] = qtu[(gp + 8) * QSC + ks * 8 + tid4];
        aL[ks][2] = qtu[gp * QSC + ks * 8 + tid4 + 4];
        aL[ks][3] = qtu[(gp + 8) * QSC + ks * 8 + tid4 + 4];
        aH[ks][0] = qtu[(16 + gp) * QSC + ks * 8 + tid4];
        aH[ks][1] = qtu[(24 + gp) * QSC + ks * 8 + tid4];
        aH[ks][2] = qtu[(16 + gp) * QSC + ks * 8 + tid4 + 4];
        aH[ks][3] = qtu[(24 + gp) * QSC + ks * 8 + tid4 + 4];
    }

    // ========= Phase 1: 2^(Q@K^T - 4) -> fp16 smem, fused row sums ===========
    float ps0 = 0.f, ps1 = 0.f, ps2 = 0.f, ps3 = 0.f;
    {
        const int colbase = warp * 128;
        #pragma unroll
        for (int g = 0; g < 4; g++) {
            const int ng = colbase + g * 32;
            float A[4][4], B[4][4];
            #pragma unroll
            for (int i = 0; i < 4; i++)
                #pragma unroll
                for (int j = 0; j < 4; j++) { A[i][j] = -4.0f; B[i][j] = -4.0f; }

            // 2-stage K pipeline: prefetch ks+1 before issuing current mma batch
            uint4 f0 = *(const uint4*)(kp + (size_t)tid4 * SS + ng + gp * 4);
            uint4 f1 = *(const uint4*)(kp + (size_t)(4 + tid4) * SS + ng + gp * 4);
            #pragma unroll
            for (int ks = 0; ks < 4; ks++) {
                uint4 n0, n1;
                if (ks < 3) {
                    n0 = *(const uint4*)(kp + (size_t)((ks + 1) * 8 + tid4) * SS + ng + gp * 4);
                    n1 = *(const uint4*)(kp + (size_t)((ks + 1) * 8 + 4 + tid4) * SS + ng + gp * 4);
                }
                mma_f16(A[0][0],A[0][1],A[0][2],A[0][3], aL[ks][0],aL[ks][1],aL[ks][2],aL[ks][3], f0.x,f1.x);
                mma_f16(A[1][0],A[1][1],A[1][2],A[1][3], aL[ks][0],aL[ks][1],aL[ks][2],aL[ks][3], f0.y,f1.y);
                mma_f16(A[2][0],A[2][1],A[2][2],A[2][3], aL[ks][0],aL[ks][1],aL[ks][2],aL[ks][3], f0.z,f1.z);
                mma_f16(A[3][0],A[3][1],A[3][2],A[3][3], aL[ks][0],aL[ks][1],aL[ks][2],aL[ks][3], f0.w,f1.w);
                mma_f16(B[0][0],B[0][1],B[0][2],B[0][3], aH[ks][0],aH[ks][1],aH[ks][2],aH[ks][3], f0.x,f1.x);
                mma_f16(B[1][0],B[1][1],B[1][2],B[1][3], aH[ks][0],aH[ks][1],aH[ks][2],aH[ks][3], f0.y,f1.y);
                mma_f16(B[2][0],B[2][1],B[2][2],B[2][3], aH[ks][0],aH[ks][1],aH[ks][2],aH[ks][3], f0.z,f1.z);
                mma_f16(B[3][0],B[3][1],B[3][2],B[3][3], aH[ks][0],aH[ks][1],aH[ks][2],aH[ks][3], f0.w,f1.w);
                if (ks < 3) { f0 = n0; f1 = n1; }
            }

            float eA[4][4], eB[4][4];
            #pragma unroll
            for (int c = 0; c < 4; c++) {
                eA[c][0] = ex2(A[c][0]); eA[c][1] = ex2(A[c][1]);
                eA[c][2] = ex2(A[c][2]); eA[c][3] = ex2(A[c][3]);
                eB[c][0] = ex2(B[c][0]); eB[c][1] = ex2(B[c][1]);
                eB[c][2] = ex2(B[c][2]); eB[c][3] = ex2(B[c][3]);
                ps0 += eA[c][0] + eA[c][1];
                ps1 += eA[c][2] + eA[c][3];
                ps2 += eB[c][0] + eB[c][1];
                ps3 += eB[c][2] + eB[c][3];
            }
            const int cell = ng / 2 + tid4 * 4;
            uint4 r0, r1, r2, r3;
            r0.x = packh2(eA[0][0], eA[1][0]); r0.y = packh2(eA[2][0], eA[3][0]);
            r0.z = packh2(eA[0][1], eA[1][1]); r0.w = packh2(eA[2][1], eA[3][1]);
            r1.x = packh2(eA[0][2], eA[1][2]); r1.y = packh2(eA[2][2], eA[3][2]);
            r1.z = packh2(eA[0][3], eA[1][3]); r1.w = packh2(eA[2][3], eA[3][3]);
            r2.x = packh2(eB[0][0], eB[1][0]); r2.y = packh2(eB[2][0], eB[3][0]);
            r2.z = packh2(eB[0][1], eB[1][1]); r2.w = packh2(eB[2][1], eB[3][1]);
            r3.x = packh2(eB[0][2], eB[1][2]); r3.y = packh2(eB[2][2], eB[3][2]);
            r3.z = packh2(eB[0][3], eB[1][3]); r3.w = packh2(eB[2][3], eB[3][3]);
            *(uint4*)(lg + gp * LSC + cell)        = r0;
            *(uint4*)(lg + (gp + 8) * LSC + cell)  = r1;
            *(uint4*)(lg + (16 + gp) * LSC + cell) = r2;
            *(uint4*)(lg + (24 + gp) * LSC + cell) = r3;
        }
    }

    // ---- prefetch V for iter 0 (independent of syncs) ----
    uint4 vg0, vg1, vh0, vh1;
    {
        const int kc = warp * 64;
        vg0 = *(const uint4*)(vp + (size_t)(kc + tid4) * 64 + gp * 4);
        vg1 = *(const uint4*)(vp + (size_t)(kc + 4 + tid4) * 64 + gp * 4);
        vh0 = *(const uint4*)(vp + (size_t)(kc + tid4) * 64 + 32 + gp * 4);
        vh1 = *(const uint4*)(vp + (size_t)(kc + 4 + tid4) * 64 + 32 + gp * 4);
    }

    // ---- row-sum reduction ----
    ps0 += __shfl_xor_sync(0xffffffffu, ps0, 1);
    ps0 += __shfl_xor_sync(0xffffffffu, ps0, 2);
    ps1 += __shfl_xor_sync(0xffffffffu, ps1, 1);
    ps1 += __shfl_xor_sync(0xffffffffu, ps1, 2);
    ps2 += __shfl_xor_sync(0xffffffffu, ps2, 1);
    ps2 += __shfl_xor_sync(0xffffffffu, ps2, 2);
    ps3 += __shfl_xor_sync(0xffffffffu, ps3, 1);
    ps3 += __shfl_xor_sync(0xffffffffu, ps3, 2);
    __syncthreads();
    if (tid4 == 0) {
        part[warp * 32 + gp]      = ps0;
        part[warp * 32 + 8 + gp]  = ps1;
        part[warp * 32 + 16 + gp] = ps2;
        part[warp * 32 + 24 + gp] = ps3;
    }
    __syncthreads();
    if (t < 32) {
        float s = 0.0f;
        #pragma unroll
        for (int w = 0; w < 16; w++) s += part[w * 32 + t];
        sums[t] = 1.0f / s;
    }
    __syncthreads();

    // ========= Phase 2+3 fused: V pipelined, score STG overlapped with mma ===
    float cA[8][4], cB[8][4];
    #pragma unroll
    for (int i = 0; i < 8; i++)
        #pragma unroll
        for (int j = 0; j < 4; j++) { cA[i][j] = 0.0f; cB[i][j] = 0.0f; }

    const int colbase = warp * 128;
    #pragma unroll
    for (int ks2 = 0; ks2 < 8; ks2++) {
        const int kc = warp * 64 + ks2 * 8;

        // ---- prefetch V for next iter (longest latency first) ----
        uint4 ng0, ng1, nh0, nh1;
        if (ks2 < 7) {
            const int nkc = kc + 8;
            ng0 = *(const uint4*)(vp + (size_t)(nkc + tid4) * 64 + gp * 4);
            ng1 = *(const uint4*)(vp + (size_t)(nkc + 4 + tid4) * 64 + gp * 4);
            nh0 = *(const uint4*)(vp + (size_t)(nkc + tid4) * 64 + 32 + gp * 4);
            nh1 = *(const uint4*)(vp + (size_t)(nkc + 4 + tid4) * 64 + 32 + gp * 4);
        }

        // ---- P A-fragments from lg (consumed by mma below) ----
        unsigned l0 = lg[gp * LSC + kc + tid4];
        unsigned l1 = lg[(gp + 8) * LSC + kc + tid4];
        unsigned l2 = lg[gp * LSC + kc + tid4 + 4];
        unsigned l3 = lg[(gp + 8) * LSC + kc + tid4 + 4];
        unsigned h0 = lg[(16 + gp) * LSC + kc + tid4];
        unsigned h1 = lg[(24 + gp) * LSC + kc + tid4];
        unsigned h2 = lg[(16 + gp) * LSC + kc + tid4 + 4];
        unsigned h3 = lg[(24 + gp) * LSC + kc + tid4 + 4];

        // ---- score STG for rows 4*ks2 .. 4*ks2+3 (independent work) ----
        #pragma unroll
        for (int rr = 0; rr < 4; rr++) {
            const int r = ks2 * 4 + rr;
            float inv = sums[r];
            uint2 u = *(const uint2*)(lg + (size_t)r * LSC + colbase / 2 + lane * 2);
            float2 x0 = unpackh2(u.x);
            float2 x1 = unpackh2(u.y);
            float4 o = make_float4(x0.x * inv, x0.y * inv, x1.x * inv, x1.y * inv);
            stg_cs4(score + ((size_t)bh * SS + q0 + r) * SS + colbase + lane * 4, o);
        }

        mma_f16(cA[0][0],cA[0][1],cA[0][2],cA[0][3], l0,l1,l2,l3, vg0.x,vg1.x);
        mma_f16(cA[1][0],cA[1][1],cA[1][2],cA[1][3], l0,l1,l2,l3, vg0.y,vg1.y);
        mma_f16(cA[2][0],cA[2][1],cA[2][2],cA[2][3], l0,l1,l2,l3, vg0.z,vg1.z);
        mma_f16(cA[3][0],cA[3][1],cA[3][2],cA[3][3], l0,l1,l2,l3, vg0.w,vg1.w);
        mma_f16(cA[4][0],cA[4][1],cA[4][2],cA[4][3], l0,l1,l2,l3, vh0.x,vh1.x);
        mma_f16(cA[5][0],cA[5][1],cA[5][2],cA[5][3], l0,l1,l2,l3, vh0.y,vh1.y);
        mma_f16(cA[6][0],cA[6][1],cA[6][2],cA[6][3], l0,l1,l2,l3, vh0.z,vh1.z);
        mma_f16(cA[7][0],cA[7][1],cA[7][2],cA[7][3], l0,l1,l2,l3, vh0.w,vh1.w);
        mma_f16(cB[0][0],cB[0][1],cB[0][2],cB[0][3], h0,h1,h2,h3, vg0.x,vg1.x);
        mma_f16(cB[1][0],cB[1][1],cB[1][2],cB[1][3], h0,h1,h2,h3, vg0.y,vg1.y);
        mma_f16(cB[2][0],cB[2][1],cB[2][2],cB[2][3], h0,h1,h2,h3, vg0.z,vg1.z);
        mma_f16(cB[3][0],cB[3][1],cB[3][2],cB[3][3], h0,h1,h2,h3, vg0.w,vg1.w);
        mma_f16(cB[4][0],cB[4][1],cB[4][2],cB[4][3], h0,h1,h2,h3, vh0.x,vh1.x);
        mma_f16(cB[5][0],cB[5][1],cB[5][2],cB[5][3], h0,h1,h2,h3, vh0.y,vh1.y);
        mma_f16(cB[6][0],cB[6][1],cB[6][2],cB[6][3], h0,h1,h2,h3, vh0.z,vh1.z);
        mma_f16(cB[7][0],cB[7][1],cB[7][2],cB[7][3], h0,h1,h2,h3, vh0.w,vh1.w);

        if (ks2 < 7) { vg0 = ng0; vg1 = ng1; vh0 = nh0; vh1 = nh1; }
    }
    __syncthreads();   // all lg reads done before red overlays it

    // ---- cross-warp reduction: fp16 packed (x 1/16), conflict-free RCS=48 ----
    {
        unsigned* base = redu + warp * (TQ * RCS);
        #pragma unroll
        for (int h = 0; h < 2; h++) {
            const int cell = h * 16 + tid4 * 4;
            uint4 r0, r1, r2, r3;
            r0.x = packh2(cA[h*4+0][0]*0.0625f, cA[h*4+1][0]*0.0625f);
            r0.y = packh2(cA[h*4+2][0]*0.0625f, cA[h*4+3][0]*0.0625f);
            r0.z = packh2(cA[h*4+0][1]*0.0625f, cA[h*4+1][1]*0.0625f);
            r0.w = packh2(cA[h*4+2][1]*0.0625f, cA[h*4+3][1]*0.0625f);
            r1.x = packh2(cA[h*4+0][2]*0.0625f, cA[h*4+1][2]*0.0625f);
            r1.y = packh2(cA[h*4+2][2]*0.0625f, cA[h*4+3][2]*0.0625f);
            r1.z = packh2(cA[h*4+0][3]*0.0625f, cA[h*4+1][3]*0.0625f);
            r1.w = packh2(cA[h*4+2][3]*0.0625f, cA[h*4+3][3]*0.0625f);
            r2.x = packh2(cB[h*4+0][0]*0.0625f, cB[h*4+1][0]*0.0625f);
            r2.y = packh2(cB[h*4+2][0]*0.0625f, cB[h*4+3][0]*0.0625f);
            r2.z = packh2(cB[h*4+0][1]*0.0625f, cB[h*4+1][1]*0.0625f);
            r2.w = packh2(cB[h*4+2][1]*0.0625f, cB[h*4+3][1]*0.0625f);
            r3.x = packh2(cB[h*4+0][2]*0.0625f, cB[h*4+1][2]*0.0625f);
            r3.y = packh2(cB[h*4+2][2]*0.0625f, cB[h*4+3][2]*0.0625f);
            r3.z = packh2(cB[h*4+0][3]*0.0625f, cB[h*4+1][3]*0.0625f);
            r3.w = packh2(cB[h*4+2][3]*0.0625f, cB[h*4+3][3]*0.0625f);
            *(uint4*)(base + gp * RCS + cell)        = r0;
            *(uint4*)(base + (gp + 8) * RCS + cell)  = r1;
            *(uint4*)(base + (16 + gp) * RCS + cell) = r2;
            *(uint4*)(base + (24 + gp) * RCS + cell) = r3;
        }
    }
    __syncthreads();
    {
        // 2048 outputs, 512 threads: 4 d each via uint2 (2 fp16 cells)
        int qi = t >> 4;
        int c2 = (t & 15) * 2;
        float4 s4 = make_float4(0, 0, 0, 0);
        #pragma unroll
        for (int w = 0; w < 16; w++) {
            uint2 u = *(const uint2*)(redu + w * (TQ * RCS) + qi * RCS + c2);
            float2 p0 = unpackh2(u.x);
            float2 p1 = unpackh2(u.y);
            s4.x += p0.x; s4.y += p0.y; s4.z += p1.x; s4.w += p1.y;
        }
        float inv = sums[qi] * 16.0f;
        s4.x *= inv; s4.y *= inv; s4.z *= inv; s4.w *= inv;
        *(float4*)(outp + ((size_t)bh * SS + q0 + qi) * DD + c2 * 2) = s4;
    }
}

// ---------------------------------------------------------------------------
extern "C" void kernel_launch(void* const* d_in, const int* in_sizes, int n_in,
                              void* d_out, int out_size) {
    const float* q = (const float*)d_in[0];
    const float* k = (const float*)d_in[1];
    const float* v = (const float*)d_in[2];

    float* outp  = (float*)d_out;                 // [B,H,S,D]
    float* score = outp + (size_t)BH * SS * DD;   // [B,H,S,S]

    cudaFuncSetAttribute(attn_kernel,
                         cudaFuncAttributeMaxDynamicSharedMemorySize, SMEM_BYTES);

    prep_all<<<QK_BLOCKS + V_BLOCKS, 256>>>(q, k, v);
    attn_kernel<<<BH * (SS / TQ), NT, SMEM_BYTES>>>(outp, score);
}